// round 14
// baseline (speedup 1.0000x reference)
#include <cuda_runtime.h>
#include <math.h>

#define S     768
#define CS    384
#define CP    128
#define EMB   16
#define NH    12
#define NPROJ 1152          // 3*H*E + 2*H*PQ*3 + H*PV*3
#define FEAT  2112          // H*(E + CP + PV*3 + PV)
#define UC    48            // padded combined [v(16) | lvp(24) | zero-pad(8)]
#define KD    29            // augmented K' dims

typedef unsigned long long u64;

// ---- packed fp32x2 FMA (FFMA2 — PTX-only on sm_103a) --------------------
__device__ __forceinline__ u64 pk(float x, float y) {
    u64 r; asm("mov.b64 %0, {%1,%2};" : "=l"(r) : "f"(x), "f"(y)); return r;
}
__device__ __forceinline__ float2 upk(u64 v) {
    float2 r; asm("mov.b64 {%0,%1}, %2;" : "=f"(r.x), "=f"(r.y) : "l"(v)); return r;
}
__device__ __forceinline__ void fma2(u64& d, u64 a, u64 b) {
    asm("fma.rn.f32x2 %0, %1, %2, %0;" : "+l"(d) : "l"(a), "l"(b));
}
// ---- cp.async helpers -----------------------------------------------------
__device__ __forceinline__ unsigned sptr(const void* p) {
    return (unsigned)__cvta_generic_to_shared(p);
}
#define CP16(dst, src) asm volatile("cp.async.cg.shared.global [%0], [%1], 16;" :: "r"(dst), "l"(src))
#define CP_COMMIT()    asm volatile("cp.async.commit_group;")
#define CP_WAIT1()     asm volatile("cp.async.wait_group 1;" ::: "memory")

// ---------------- scratch (device globals) --------------------------------
__device__ float g_P[S * NPROJ];
__device__ float g_qp2[NH * S * 32];
__device__ float g_kp2[NH * KD * S];
__device__ float g_U[NH * S * UC];
__device__ float g_wpair[NH * S * S];
__device__ float g_a[NH * S * S];
__device__ float g_asp[NH * 48 * S];      // per-block column partials
__device__ float g_asumT[S * NH];
__device__ float g_feat[S * FEAT];
__device__ float g_out2[2 * S * CS];

// ---------------- K0: filler (positions k_wpair at launch #4 for ncu) ------
__global__ void k_pre() {
    int x = blockIdx.x * 256 + threadIdx.x;
    if (x < S * NH) g_asumT[x] = 0.0f;       // overwritten by k_asum2 later
}

// ---------------- K1: packed projection GEMM (reg double-buffered) --------
__global__ void k_proj(const float* __restrict__ single,
                       const float* __restrict__ Wq, const float* __restrict__ Wk,
                       const float* __restrict__ Wv, const float* __restrict__ Wqp,
                       const float* __restrict__ Wkp, const float* __restrict__ Wvp) {
    __shared__ float As[32 * 36];
    __shared__ float Bs[32 * 68];
    const int n0 = blockIdx.x * 64, m0 = blockIdx.y * 32;
    const int t  = threadIdx.x;
    const int i0 = (t & 15) * 2, j0 = (t >> 4) * 4;

    const float* asrc[4]; int aidx[4];
#pragma unroll
    for (int r = 0; r < 4; r++) {
        int idx = t + 256 * r;
        int i = idx >> 5, k = idx & 31;
        asrc[r] = single + (m0 + i) * CS + k;
        aidx[r] = k * 36 + i;
    }
    const float* bsrc[8]; int bidx[8];
#pragma unroll
    for (int r = 0; r < 8; r++) {
        int idx = t + 256 * r;
        int j = idx >> 5, k = idx & 31;
        int n = n0 + j;
        const float* row;
        if (n < 192)      row = Wq  + n * CS;
        else if (n < 384) row = Wk  + (n - 192) * CS;
        else if (n < 576) row = Wv  + (n - 384) * CS;
        else if (n < 720) row = Wqp + (n - 576) * CS;
        else if (n < 864) row = Wkp + (n - 720) * CS;
        else              row = Wvp + (n - 864) * CS;
        bsrc[r] = row + k;
        bidx[r] = k * 68 + j;
    }
    u64 acc[2][2] = {};
    float ra[4], rb[8];
#pragma unroll
    for (int r = 0; r < 4; r++) ra[r] = asrc[r][0];
#pragma unroll
    for (int r = 0; r < 8; r++) rb[r] = bsrc[r][0];

    for (int kt = 0; kt < CS; kt += 32) {
#pragma unroll
        for (int r = 0; r < 4; r++) As[aidx[r]] = ra[r];
#pragma unroll
        for (int r = 0; r < 8; r++) Bs[bidx[r]] = rb[r];
        __syncthreads();
        if (kt + 32 < CS) {
#pragma unroll
            for (int r = 0; r < 4; r++) ra[r] = asrc[r][kt + 32];
#pragma unroll
            for (int r = 0; r < 8; r++) rb[r] = bsrc[r][kt + 32];
        }
#pragma unroll
        for (int k = 0; k < 32; k++) {
            float2 a2 = *(const float2*)&As[k * 36 + i0];
            float4 b4 = *(const float4*)&Bs[k * 68 + j0];
            u64 bxy = pk(b4.x, b4.y), bzw = pk(b4.z, b4.w);
            u64 ax = pk(a2.x, a2.x), ay = pk(a2.y, a2.y);
            fma2(acc[0][0], ax, bxy); fma2(acc[0][1], ax, bzw);
            fma2(acc[1][0], ay, bxy); fma2(acc[1][1], ay, bzw);
        }
        __syncthreads();
    }
#pragma unroll
    for (int ii = 0; ii < 2; ii++) {
        float2 lo = upk(acc[ii][0]), hi = upk(acc[ii][1]);
        float* o = &g_P[(m0 + i0 + ii) * NPROJ + n0 + j0];
        o[0] = lo.x; o[1] = lo.y; o[2] = hi.x; o[3] = hi.y;
    }
}

// ---------------- K1b: frame apply + augmented Q'/K' build ----------------
__global__ void k_frames(const float* __restrict__ rot, const float* __restrict__ trans,
                         const float* __restrict__ gamma) {
    int idx = blockIdx.x * blockDim.x + threadIdx.x;
    if (idx >= NH * S) return;
    int h = idx / S, s = idx % S;

    float g  = gamma[h];
    float sp = (g > 20.f) ? g : log1pf(expf(g));
    float cf = -0.11785113f * sp;

    float R[3][3], tv[3];
#pragma unroll
    for (int a = 0; a < 3; a++) {
        tv[a] = trans[s * 3 + a];
#pragma unroll
        for (int b = 0; b < 3; b++) R[a][b] = rot[s * 9 + a * 3 + b];
    }
    const float* Ps = g_P + (size_t)s * NPROJ;
    float* qp2 = g_qp2 + (size_t)(h * S + s) * 32;

#pragma unroll
    for (int e = 0; e < EMB; e++) {
        qp2[e] = 0.25f * Ps[h * EMB + e];
        g_kp2[(h * KD + e) * S + s]        = Ps[192 + h * EMB + e];
        g_U[(size_t)(h * S + s) * UC + e]  = Ps[384 + h * EMB + e];
    }
    float m2cf = -2.0f * cf;
#pragma unroll
    for (int p = 0; p < 4; p++) {
        float x0 = Ps[576 + h * 12 + p * 3 + 0];
        float x1 = Ps[576 + h * 12 + p * 3 + 1];
        float x2 = Ps[576 + h * 12 + p * 3 + 2];
#pragma unroll
        for (int a = 0; a < 3; a++) {
            float l = R[a][0] * x0 + R[a][1] * x1 + R[a][2] * x2 + tv[a];
            qp2[16 + p * 3 + a] = m2cf * l;
        }
    }
    qp2[28] = 1.0f; qp2[29] = 0.0f; qp2[30] = 0.0f; qp2[31] = 0.0f;

    float nk = 0.0f;
#pragma unroll
    for (int p = 0; p < 4; p++) {
        float x0 = Ps[720 + h * 12 + p * 3 + 0];
        float x1 = Ps[720 + h * 12 + p * 3 + 1];
        float x2 = Ps[720 + h * 12 + p * 3 + 2];
#pragma unroll
        for (int a = 0; a < 3; a++) {
            float l = R[a][0] * x0 + R[a][1] * x1 + R[a][2] * x2 + tv[a];
            g_kp2[(h * KD + 16 + p * 3 + a) * S + s] = l;
            nk += l * l;
        }
    }
    g_kp2[(h * KD + 28) * S + s] = cf * nk;

#pragma unroll
    for (int p = 0; p < 8; p++) {
        float x0 = Ps[864 + h * 24 + p * 3 + 0];
        float x1 = Ps[864 + h * 24 + p * 3 + 1];
        float x2 = Ps[864 + h * 24 + p * 3 + 2];
#pragma unroll
        for (int a = 0; a < 3; a++)
            g_U[(size_t)(h * S + s) * UC + 16 + p * 3 + a] =
                R[a][0] * x0 + R[a][1] * x1 + R[a][2] * x2 + tv[a];
    }
#pragma unroll
    for (int c = 40; c < UC; c++) g_U[(size_t)(h * S + s) * UC + c] = 0.0f;
}

// ---------------- K2: w_pair — warp-private rings, 32-j chunks, 5 blk/SM ---
// warp w owns j-sub-slice [c*32 + w*8, +8); thread = (jq: 1 j, hq: 3 h).
__global__ void __launch_bounds__(128) k_wpair(const float* __restrict__ pair,
                                               const float* __restrict__ Wb) {
    extern __shared__ float sm[];
    float4* buf = (float4*)sm;                 // [4 warps][2 stages][8 j][32 q4]
    float*  swb = sm + 4 * 2 * 8 * 32 * 4;     // [12][132]
    const int i = blockIdx.x;
    const int t = threadIdx.x;
    const int lane = t & 31, w = t >> 5;

    for (int x = t; x < NH * CP; x += 128) swb[(x >> 7) * 132 + (x & 127)] = Wb[x];

    float4* wbuf = buf + w * 512;              // this warp's 2-stage ring
    const float4* gp = (const float4*)pair + ((size_t)i * S + w * 8) * 32;

    // prefetch chunk 0: 8 rows, lane = q
#pragma unroll
    for (int r = 0; r < 8; r++)
        CP16(sptr(&wbuf[r * 32 + ((lane + r) & 31)]), gp + r * 32 + lane);
    CP_COMMIT();
    __syncthreads();                           // Wb visible to all warps

    const int jq = lane >> 2, hq = lane & 3;
    const int h0 = hq * 3;

    for (int c = 0; c < 24; c++) {
        float4* cur = wbuf + (c & 1) * 256;
        if (c + 1 < 24) {
            float4* nxt = wbuf + ((c + 1) & 1) * 256;
            const float4* gsrc = gp + (size_t)(c + 1) * 32 * 32;
#pragma unroll
            for (int r = 0; r < 8; r++)
                CP16(sptr(&nxt[r * 32 + ((lane + r) & 31)]), gsrc + r * 32 + lane);
        }
        CP_COMMIT();
        CP_WAIT1();                            // per-warp wait, no bar.sync

        u64 acc[3][2] = {};
#pragma unroll
        for (int q = 0; q < 32; q++) {
            float4 pa = cur[jq * 32 + ((q + jq) & 31)];       // 1-phase LDS.128
            u64 a0 = pk(pa.x, pa.y), a1 = pk(pa.z, pa.w);
#pragma unroll
            for (int r = 0; r < 3; r++) {
                float4 wv = *(const float4*)&swb[(h0 + r) * 132 + q * 4];
                fma2(acc[r][0], a0, pk(wv.x, wv.y));
                fma2(acc[r][1], a1, pk(wv.z, wv.w));
            }
        }
        int jg = c * 32 + w * 8 + jq;
#pragma unroll
        for (int r = 0; r < 3; r++) {
            float2 xa = upk(acc[r][0]), ya = upk(acc[r][1]);
            g_wpair[((size_t)(h0 + r) * S + i) * S + jg] = xa.x + xa.y + ya.x + ya.y;
        }
    }
}

// ---------------- K3: logits + softmax + fused block column-sums -----------
__global__ void __launch_bounds__(512, 2) k_soft() {
    extern __shared__ float sm[];
    float* ks = sm;                        // [29][768]; reused as stage [16][768]
    float* sq = sm + KD * S;               // [16 rows][32]
    const int h  = blockIdx.y;
    const int i0 = blockIdx.x * 16;
    const int t  = threadIdx.x;

    for (int x = t; x < KD * S; x += 512) ks[x] = g_kp2[(size_t)h * KD * S + x];
    sq[t] = g_qp2[(size_t)(h * S + i0 + (t >> 5)) * 32 + (t & 31)];
    __syncthreads();

    const int w = t >> 5, lane = t & 31;
    const int i = i0 + w;
    const float* wp = g_wpair + ((size_t)h * S + i) * S + lane * 4;

    u64 lo[6], hi[6];
#pragma unroll
    for (int b = 0; b < 6; b++) {
        float4 v = *(const float4*)&wp[b * 128];
        lo[b] = pk(v.x, v.y); hi[b] = pk(v.z, v.w);
    }
#pragma unroll
    for (int e = 0; e < KD; e++) {
        float qe = sq[w * 32 + e];
        u64 q2 = pk(qe, qe);
        const float* kr = ks + e * S + lane * 4;
#pragma unroll
        for (int b = 0; b < 6; b++) {
            float4 kk = *(const float4*)&kr[b * 128];
            fma2(lo[b], q2, pk(kk.x, kk.y));
            fma2(hi[b], q2, pk(kk.z, kk.w));
        }
    }

    float4 l4[6];
    float m = -1e30f;
#pragma unroll
    for (int b = 0; b < 6; b++) {
        float2 a = upk(lo[b]), c = upk(hi[b]);
        l4[b] = make_float4(a.x, a.y, c.x, c.y);
        m = fmaxf(m, fmaxf(fmaxf(a.x, a.y), fmaxf(c.x, c.y)));
    }
#pragma unroll
    for (int o = 16; o > 0; o >>= 1) m = fmaxf(m, __shfl_xor_sync(0xffffffffu, m, o));
    float sum = 0.0f;
#pragma unroll
    for (int b = 0; b < 6; b++) {
        l4[b].x = __expf(l4[b].x - m); l4[b].y = __expf(l4[b].y - m);
        l4[b].z = __expf(l4[b].z - m); l4[b].w = __expf(l4[b].w - m);
        sum += (l4[b].x + l4[b].y) + (l4[b].z + l4[b].w);
    }
#pragma unroll
    for (int o = 16; o > 0; o >>= 1) sum += __shfl_xor_sync(0xffffffffu, sum, o);
    float inv = 1.0f / sum;
    float4 o4[6];
#pragma unroll
    for (int b = 0; b < 6; b++)
        o4[b] = make_float4(l4[b].x * inv, l4[b].y * inv, l4[b].z * inv, l4[b].w * inv);
    float* ap = g_a + ((size_t)h * S + i) * S + lane * 4;
#pragma unroll
    for (int b = 0; b < 6; b++) *(float4*)&ap[b * 128] = o4[b];

    // fused column partial sums (deterministic; reuse ks as [16][768] stage)
    __syncthreads();
    float* stage = ks;
#pragma unroll
    for (int b = 0; b < 6; b++)
        *(float4*)&stage[w * S + lane * 4 + b * 128] = o4[b];
    __syncthreads();
    for (int x = t; x < S; x += 512) {
        float s = 0.f;
#pragma unroll
        for (int r = 0; r < 16; r++) s += stage[r * S + x];
        g_asp[((size_t)h * 48 + blockIdx.x) * S + x] = s;
    }
}

// ---------------- K4: finish column sums ------------------------------------
__global__ void k_asum2() {
    int X = blockIdx.x * 128 + threadIdx.x;      // 0 .. NH*S-1
    int h = X / S, j = X - h * S;
    float s = 0.f;
#pragma unroll 8
    for (int b = 0; b < 48; b++) s += g_asp[((size_t)h * 48 + b) * S + j];
    g_asumT[j * NH + h] = s;
}

// ---------------- K5: o_combined = a @ U + fused inverse-frame scatter -----
__global__ void __launch_bounds__(256) k_av(const float* __restrict__ rot,
                                            const float* __restrict__ trans) {
    extern __shared__ float sm[];
    float* sa = sm;                            // [2][32][132]
    float* su = sm + 2 * 32 * 132;             // [2][128][48]
    const int h  = blockIdx.y;
    const int i0 = blockIdx.x * 32;
    const int t  = threadIdx.x;
    const int i  = t & 31, c0 = (t >> 5) * 6;
    u64 acc[3] = {};

    const float4* ga = (const float4*)g_a;
    const float4* gu = (const float4*)g_U + (size_t)h * S * 12;

#pragma unroll
    for (int r = 0; r < 4; r++) {
        int idx = t + 256 * r;
        int ii = idx >> 5, j4 = idx & 31;
        CP16(sptr(&((float4*)sa)[ii * 33 + j4]),
             ga + ((size_t)h * S + i0 + ii) * (S / 4) + j4);
    }
#pragma unroll
    for (int r = 0; r < 6; r++) {
        int idx = t + 256 * r;
        CP16(sptr(&((float4*)su)[idx]), gu + idx);
    }
    CP_COMMIT();

    for (int c = 0; c < 6; c++) {
        float* sac = sa + (c & 1) * 32 * 132;
        float* suc = su + (c & 1) * 128 * 48;
        if (c + 1 < 6) {
            float* san = sa + ((c + 1) & 1) * 32 * 132;
            float* sun = su + ((c + 1) & 1) * 128 * 48;
            int jt4 = (c + 1) * 32;
#pragma unroll
            for (int r = 0; r < 4; r++) {
                int idx = t + 256 * r;
                int ii = idx >> 5, j4 = idx & 31;
                CP16(sptr(&((float4*)san)[ii * 33 + j4]),
                     ga + ((size_t)h * S + i0 + ii) * (S / 4) + jt4 + j4);
            }
            const float4* gun = gu + (c + 1) * 128 * 12;
#pragma unroll
            for (int r = 0; r < 6; r++) {
                int idx = t + 256 * r;
                CP16(sptr(&((float4*)sun)[idx]), gun + idx);
            }
        }
        CP_COMMIT();
        CP_WAIT1();
        __syncthreads();

#pragma unroll 4
        for (int j = 0; j < 128; j++) {
            float av = sac[i * 132 + j];
            u64 p = pk(av, av);
            const u64* uu = (const u64*)&suc[j * UC + c0];
            fma2(acc[0], p, uu[0]); fma2(acc[1], p, uu[1]); fma2(acc[2], p, uu[2]);
        }
        __syncthreads();
    }

    // stage oc into smem [32][49] then fused inverse-frame scatter
    float* soc = sm;
    __syncthreads();
    {
        float2 v0 = upk(acc[0]), v1 = upk(acc[1]), v2 = upk(acc[2]);
        float* d = soc + i * 49 + c0;
        d[0] = v0.x; d[1] = v0.y; d[2] = v1.x; d[3] = v1.y; d[4] = v2.x; d[5] = v2.y;
    }
    __syncthreads();

    if (t < 32) {
        int s = i0 + t;
        const float* oc = soc + t * 49;
        float* f = g_feat + (size_t)s * FEAT;
#pragma unroll
        for (int e = 0; e < EMB; e++) f[h * EMB + e] = oc[e];

        float R[3][3], tv[3];
#pragma unroll
        for (int a = 0; a < 3; a++) {
            tv[a] = trans[s * 3 + a];
#pragma unroll
            for (int b = 0; b < 3; b++) R[a][b] = rot[s * 9 + a * 3 + b];
        }
#pragma unroll
        for (int p = 0; p < 8; p++) {
            float x0 = oc[16 + p * 3 + 0] - tv[0];
            float x1 = oc[16 + p * 3 + 1] - tv[1];
            float x2 = oc[16 + p * 3 + 2] - tv[2];
            float og[3];
#pragma unroll
            for (int a = 0; a < 3; a++) og[a] = R[0][a] * x0 + R[1][a] * x1 + R[2][a] * x2;
#pragma unroll
            for (int a = 0; a < 3; a++) f[1728 + p * 36 + h * 3 + a] = og[a];
            f[2016 + p * 12 + h] = sqrtf(og[0] * og[0] + og[1] * og[1] + og[2] * og[2]);
        }
    }
}

// ---------------- K7: o_pair — pipelined pair + asum slices, LDS.128 --------
__global__ void __launch_bounds__(256) k_opair(const float* __restrict__ pair) {
    extern __shared__ float sm[];
    float4* buf  = (float4*)sm;                // [2][64*32] pair chunks
    float*  sasb = sm + 2 * 64 * 32 * 4;       // [2][768] asum slices
    const int i = blockIdx.x;
    const int t = threadIdx.x;
    const int c4 = t & 31, kk = t >> 5;

    const float4* gp = (const float4*)pair + (size_t)i * S * 32;
    const float4* gs = (const float4*)g_asumT;     // 2304 float4 total
#pragma unroll
    for (int r = 0; r < 8; r++) {
        int idx = t + 256 * r;
        CP16(sptr(&buf[idx]), gp + idx);
    }
    if (t < 192) CP16(sptr(&((float4*)sasb)[t]), gs + t);
    CP_COMMIT();

    u64 acc[4][6] = {};
    for (int c = 0; c < 12; c++) {
        float4* cur  = buf  + (c & 1) * (64 * 32);
        const float* scur = sasb + (c & 1) * 768;
        if (c + 1 < 12) {
            float4* nxt = buf + ((c + 1) & 1) * (64 * 32);
            float*  snx = sasb + ((c + 1) & 1) * 768;
            const float4* gsrc = gp + (c + 1) * 64 * 32;
#pragma unroll
            for (int r = 0; r < 8; r++) {
                int idx = t + 256 * r;
                CP16(sptr(&nxt[idx]), gsrc + idx);
            }
            if (t < 192) CP16(sptr(&((float4*)snx)[t]), gs + (c + 1) * 192 + t);
        }
        CP_COMMIT();
        CP_WAIT1();
        __syncthreads();

#pragma unroll 4
        for (int kl = kk; kl < 64; kl += 8) {
            float4 p = cur[kl * 32 + c4];
            const float4* au4 = (const float4*)&scur[kl * 12];   // 3x LDS.128, bcast
            float4 A0 = au4[0], A1 = au4[1], A2 = au4[2];
            u64 a0 = pk(A0.x, A0.y), a1 = pk(A0.z, A0.w);
            u64 a2 = pk(A1.x, A1.y), a3 = pk(A1.z, A1.w);
            u64 a4 = pk(A2.x, A2.y), a5 = pk(A2.z, A2.w);
            u64 px = pk(p.x, p.x), py = pk(p.y, p.y), pz = pk(p.z, p.z), pw = pk(p.w, p.w);
            fma2(acc[0][0], px, a0); fma2(acc[0][1], px, a1); fma2(acc[0][2], px, a2);
            fma2(acc[0][3], px, a3); fma2(acc[0][4], px, a4); fma2(acc[0][5], px, a5);
            fma2(acc[1][0], py, a0); fma2(acc[1][1], py, a1); fma2(acc[1][2], py, a2);
            fma2(acc[1][3], py, a3); fma2(acc[1][4], py, a4); fma2(acc[1][5], py, a5);
            fma2(acc[2][0], pz, a0); fma2(acc[2][1], pz, a1); fma2(acc[2][2], pz, a2);
            fma2(acc[2][3], pz, a3); fma2(acc[2][4], pz, a4); fma2(acc[2][5], pz, a5);
            fma2(acc[3][0], pw, a0); fma2(acc[3][1], pw, a1); fma2(acc[3][2], pw, a2);
            fma2(acc[3][3], pw, a3); fma2(acc[3][4], pw, a4); fma2(acc[3][5], pw, a5);
        }
        __syncthreads();
    }

    float rv[48];
#pragma unroll
    for (int cc = 0; cc < 4; cc++)
#pragma unroll
        for (int hp = 0; hp < 6; hp++) {
            float2 v = upk(acc[cc][hp]);
            rv[cc * 12 + 2 * hp]     = v.x;
            rv[cc * 12 + 2 * hp + 1] = v.y;
        }

    float* red = sm;
#pragma unroll
    for (int step = 4; step >= 1; step >>= 1) {
        if (kk >= step && kk < 2 * step) {
            float* d = red + ((kk - step) * 32 + c4) * 48;
#pragma unroll
            for (int x = 0; x < 48; x += 4)
                *(float4*)&d[x] = make_float4(rv[x], rv[x + 1], rv[x + 2], rv[x + 3]);
        }
        __syncthreads();
        if (kk < step) {
            const float* d = red + (kk * 32 + c4) * 48;
#pragma unroll
            for (int x = 0; x < 48; x++) rv[x] += d[x];
        }
        __syncthreads();
    }
    if (kk == 0) {
        float* f = g_feat + (size_t)i * FEAT + 192 + c4 * 4;
#pragma unroll
        for (int hh = 0; hh < 12; hh++)
            *(float4*)&f[hh * CP] =
                make_float4(rv[hh], rv[12 + hh], rv[24 + hh], rv[36 + hh]);
    }
}

// ---------------- K8: out partials = feat @ Wo^T (split-K=2, reg-db) -------
__global__ void k_out(const float* __restrict__ Wo) {
    __shared__ float As[32 * 68];
    __shared__ float Bs[32 * 68];
    const int n0 = blockIdx.x * 64, m0 = blockIdx.y * 64, z = blockIdx.z;
    const int t  = threadIdx.x;
    const int i0 = (t & 15) * 4, j0 = (t >> 4) * 4;
    const int kbase = z * (FEAT / 2);

    int aoff[8], boff[8], aidx[8], bidx[8];
#pragma unroll
    for (int r = 0; r < 8; r++) {
        int idx = t + 256 * r;
        int i = idx >> 5, k = idx & 31;
        aoff[r] = (m0 + i) * FEAT + kbase + k;
        aidx[r] = k * 68 + i;
        boff[r] = (n0 + i) * FEAT + kbase + k;
        bidx[r] = k * 68 + i;
    }
    u64 acc[4][2] = {};
    float ra[8], rb[8];
#pragma unroll
    for (int r = 0; r < 8; r++) { ra[r] = g_feat[aoff[r]]; rb[r] = Wo[boff[r]]; }

    for (int kt = 0; kt < FEAT / 2; kt += 32) {
#pragma unroll
        for (int r = 0; r < 8; r++) { As[aidx[r]] = ra[r]; Bs[bidx[r]] = rb[r]; }
        __syncthreads();
        if (kt + 32 < FEAT / 2) {
#pragma unroll
            for (int r = 0; r < 8; r++) {
                ra[r] = g_feat[aoff[r] + kt + 32];
                rb[r] = Wo[boff[r] + kt + 32];
            }
        }
#pragma unroll
        for (int k = 0; k < 32; k++) {
            float4 a4 = *(const float4*)&As[k * 68 + i0];
            float4 b4 = *(const float4*)&Bs[k * 68 + j0];
            u64 bxy = pk(b4.x, b4.y), bzw = pk(b4.z, b4.w);
            float av[4] = {a4.x, a4.y, a4.z, a4.w};
#pragma unroll
            for (int ii = 0; ii < 4; ii++) {
                u64 aa = pk(av[ii], av[ii]);
                fma2(acc[ii][0], aa, bxy);
                fma2(acc[ii][1], aa, bzw);
            }
        }
        __syncthreads();
    }
#pragma unroll
    for (int ii = 0; ii < 4; ii++) {
        float2 lo = upk(acc[ii][0]), hi = upk(acc[ii][1]);
        float* o = &g_out2[(size_t)z * S * CS + (m0 + i0 + ii) * CS + n0 + j0];
        o[0] = lo.x; o[1] = lo.y; o[2] = hi.x; o[3] = hi.y;
    }
}

// ---------------- K9: combine split-K partials + bias ----------------------
__global__ void k_bias(const float* __restrict__ bo, float* __restrict__ out) {
    int x = blockIdx.x * 256 + threadIdx.x;
    float4 a = ((const float4*)g_out2)[x];
    float4 b = ((const float4*)g_out2)[S * CS / 4 + x];
    int n = (x * 4) % CS;
    float4 bb = *(const float4*)&bo[n];
    ((float4*)out)[x] = make_float4(a.x + b.x + bb.x, a.y + b.y + bb.y,
                                    a.z + b.z + bb.z, a.w + b.w + bb.w);
}

// ---------------------------------------------------------------------------
extern "C" void kernel_launch(void* const* d_in, const int* in_sizes, int n_in,
                              void* d_out, int out_size) {
    const float* single = (const float*)d_in[0];
    const float* pair   = (const float*)d_in[1];
    const float* rot    = (const float*)d_in[2];
    const float* trans  = (const float*)d_in[3];
    const float* Wq     = (const float*)d_in[4];
    const float* Wk     = (const float*)d_in[5];
    const float* Wv     = (const float*)d_in[6];
    const float* Wqp    = (const float*)d_in[7];
    const float* Wkp    = (const float*)d_in[8];
    const float* Wvp    = (const float*)d_in[9];
    const float* Wb     = (const float*)d_in[10];
    const float* Wo     = (const float*)d_in[11];
    const float* bo     = (const float*)d_in[12];
    const float* gamma  = (const float*)d_in[13];
    float* out = (float*)d_out;

    const int SMEM_WPAIR = 4 * 2 * 8 * 32 * 16 + 12 * 132 * 4;  // 39104
    const int SMEM_SOFT  = KD * S * 4 + 16 * 32 * 4;            // 91136
    const int SMEM_AV    = 2 * 32 * 132 * 4 + 2 * 128 * 48 * 4; // 82944
    const int SMEM_OPAIR = 2 * 64 * 32 * 16 + 2 * S * 4;        // 71680
    cudaFuncSetAttribute(k_wpair, cudaFuncAttributeMaxDynamicSharedMemorySize, SMEM_WPAIR);
    cudaFuncSetAttribute(k_soft,  cudaFuncAttributeMaxDynamicSharedMemorySize, SMEM_SOFT);
    cudaFuncSetAttribute(k_av,    cudaFuncAttributeMaxDynamicSharedMemorySize, SMEM_AV);
    cudaFuncSetAttribute(k_opair, cudaFuncAttributeMaxDynamicSharedMemorySize, SMEM_OPAIR);

    k_pre    <<<(S * NH + 255) / 256, 256>>>();          // filler: k_wpair -> launch #4
    k_proj   <<<dim3(NPROJ / 64, S / 32), 256>>>(single, Wq, Wk, Wv, Wqp, Wkp, Wvp);
    k_frames <<<(NH * S + 255) / 256, 256>>>(rot, trans, gamma);
    k_wpair  <<<S, 128, SMEM_WPAIR>>>(pair, Wb);
    k_soft   <<<dim3(S / 16, NH), 512, SMEM_SOFT>>>();
    k_asum2  <<<(NH * S) / 128, 128>>>();
    k_av     <<<dim3(S / 32, NH), 256, SMEM_AV>>>(rot, trans);
    k_opair  <<<S, 256, SMEM_OPAIR>>>(pair);
    k_out    <<<dim3(CS / 64, S / 64, 2), 256>>>(Wo);
    k_bias   <<<(S * CS / 4) / 256, 256>>>(bo, out);
}

// round 15
// speedup vs baseline: 1.1357x; 1.1357x over previous
#include <cuda_runtime.h>
#include <math.h>

#define S     768
#define CS    384
#define CP    128
#define EMB   16
#define NH    12
#define NPROJ 1152          // 3*H*E + 2*H*PQ*3 + H*PV*3
#define FEAT  2112          // H*(E + CP + PV*3 + PV)
#define UC    48            // padded combined [v(16) | lvp(24) | zero-pad(8)]
#define KD    29            // augmented K' dims

typedef unsigned long long u64;

// ---- packed fp32x2 FMA (FFMA2 — PTX-only on sm_103a) --------------------
__device__ __forceinline__ u64 pk(float x, float y) {
    u64 r; asm("mov.b64 %0, {%1,%2};" : "=l"(r) : "f"(x), "f"(y)); return r;
}
__device__ __forceinline__ float2 upk(u64 v) {
    float2 r; asm("mov.b64 {%0,%1}, %2;" : "=f"(r.x), "=f"(r.y) : "l"(v)); return r;
}
__device__ __forceinline__ void fma2(u64& d, u64 a, u64 b) {
    asm("fma.rn.f32x2 %0, %1, %2, %0;" : "+l"(d) : "l"(a), "l"(b));
}
// ---- cp.async helpers -----------------------------------------------------
__device__ __forceinline__ unsigned sptr(const void* p) {
    return (unsigned)__cvta_generic_to_shared(p);
}
#define CP16(dst, src) asm volatile("cp.async.cg.shared.global [%0], [%1], 16;" :: "r"(dst), "l"(src))
#define CP_COMMIT()    asm volatile("cp.async.commit_group;")
#define CP_WAIT1()     asm volatile("cp.async.wait_group 1;" ::: "memory")

// ---------------- scratch (device globals) --------------------------------
__device__ float g_P[S * NPROJ];
__device__ float g_qp2[NH * S * 32];
__device__ float g_kp2[NH * KD * S];
__device__ float g_U[NH * S * UC];
__device__ float g_wpair[NH * S * S];
__device__ float g_a[NH * S * S];
__device__ float g_asp[NH * 48 * S];      // per-block column partials
__device__ float g_asumT[S * NH];
__device__ float g_feat[S * FEAT];
__device__ float g_out2[2 * S * CS];

// ---------------- K1: packed projection GEMM (reg double-buffered) --------
__global__ void k_proj(const float* __restrict__ single,
                       const float* __restrict__ Wq, const float* __restrict__ Wk,
                       const float* __restrict__ Wv, const float* __restrict__ Wqp,
                       const float* __restrict__ Wkp, const float* __restrict__ Wvp) {
    __shared__ float As[32 * 36];
    __shared__ float Bs[32 * 68];
    const int n0 = blockIdx.x * 64, m0 = blockIdx.y * 32;
    const int t  = threadIdx.x;
    const int i0 = (t & 15) * 2, j0 = (t >> 4) * 4;

    const float* asrc[4]; int aidx[4];
#pragma unroll
    for (int r = 0; r < 4; r++) {
        int idx = t + 256 * r;
        int i = idx >> 5, k = idx & 31;
        asrc[r] = single + (m0 + i) * CS + k;
        aidx[r] = k * 36 + i;
    }
    const float* bsrc[8]; int bidx[8];
#pragma unroll
    for (int r = 0; r < 8; r++) {
        int idx = t + 256 * r;
        int j = idx >> 5, k = idx & 31;
        int n = n0 + j;
        const float* row;
        if (n < 192)      row = Wq  + n * CS;
        else if (n < 384) row = Wk  + (n - 192) * CS;
        else if (n < 576) row = Wv  + (n - 384) * CS;
        else if (n < 720) row = Wqp + (n - 576) * CS;
        else if (n < 864) row = Wkp + (n - 720) * CS;
        else              row = Wvp + (n - 864) * CS;
        bsrc[r] = row + k;
        bidx[r] = k * 68 + j;
    }
    u64 acc[2][2] = {};
    float ra[4], rb[8];
#pragma unroll
    for (int r = 0; r < 4; r++) ra[r] = asrc[r][0];
#pragma unroll
    for (int r = 0; r < 8; r++) rb[r] = bsrc[r][0];

    for (int kt = 0; kt < CS; kt += 32) {
#pragma unroll
        for (int r = 0; r < 4; r++) As[aidx[r]] = ra[r];
#pragma unroll
        for (int r = 0; r < 8; r++) Bs[bidx[r]] = rb[r];
        __syncthreads();
        if (kt + 32 < CS) {
#pragma unroll
            for (int r = 0; r < 4; r++) ra[r] = asrc[r][kt + 32];
#pragma unroll
            for (int r = 0; r < 8; r++) rb[r] = bsrc[r][kt + 32];
        }
#pragma unroll
        for (int k = 0; k < 32; k++) {
            float2 a2 = *(const float2*)&As[k * 36 + i0];
            float4 b4 = *(const float4*)&Bs[k * 68 + j0];
            u64 bxy = pk(b4.x, b4.y), bzw = pk(b4.z, b4.w);
            u64 ax = pk(a2.x, a2.x), ay = pk(a2.y, a2.y);
            fma2(acc[0][0], ax, bxy); fma2(acc[0][1], ax, bzw);
            fma2(acc[1][0], ay, bxy); fma2(acc[1][1], ay, bzw);
        }
        __syncthreads();
    }
#pragma unroll
    for (int ii = 0; ii < 2; ii++) {
        float2 lo = upk(acc[ii][0]), hi = upk(acc[ii][1]);
        float* o = &g_P[(m0 + i0 + ii) * NPROJ + n0 + j0];
        o[0] = lo.x; o[1] = lo.y; o[2] = hi.x; o[3] = hi.y;
    }
}

// ---------------- K1b: frame apply + augmented Q'/K' build ----------------
__global__ void k_frames(const float* __restrict__ rot, const float* __restrict__ trans,
                         const float* __restrict__ gamma) {
    int idx = blockIdx.x * blockDim.x + threadIdx.x;
    if (idx >= NH * S) return;
    int h = idx / S, s = idx % S;

    float g  = gamma[h];
    float sp = (g > 20.f) ? g : log1pf(expf(g));
    float cf = -0.11785113f * sp;

    float R[3][3], tv[3];
#pragma unroll
    for (int a = 0; a < 3; a++) {
        tv[a] = trans[s * 3 + a];
#pragma unroll
        for (int b = 0; b < 3; b++) R[a][b] = rot[s * 9 + a * 3 + b];
    }
    const float* Ps = g_P + (size_t)s * NPROJ;
    float* qp2 = g_qp2 + (size_t)(h * S + s) * 32;

#pragma unroll
    for (int e = 0; e < EMB; e++) {
        qp2[e] = 0.25f * Ps[h * EMB + e];
        g_kp2[(h * KD + e) * S + s]        = Ps[192 + h * EMB + e];
        g_U[(size_t)(h * S + s) * UC + e]  = Ps[384 + h * EMB + e];
    }
    float m2cf = -2.0f * cf;
#pragma unroll
    for (int p = 0; p < 4; p++) {
        float x0 = Ps[576 + h * 12 + p * 3 + 0];
        float x1 = Ps[576 + h * 12 + p * 3 + 1];
        float x2 = Ps[576 + h * 12 + p * 3 + 2];
#pragma unroll
        for (int a = 0; a < 3; a++) {
            float l = R[a][0] * x0 + R[a][1] * x1 + R[a][2] * x2 + tv[a];
            qp2[16 + p * 3 + a] = m2cf * l;
        }
    }
    qp2[28] = 1.0f; qp2[29] = 0.0f; qp2[30] = 0.0f; qp2[31] = 0.0f;

    float nk = 0.0f;
#pragma unroll
    for (int p = 0; p < 4; p++) {
        float x0 = Ps[720 + h * 12 + p * 3 + 0];
        float x1 = Ps[720 + h * 12 + p * 3 + 1];
        float x2 = Ps[720 + h * 12 + p * 3 + 2];
#pragma unroll
        for (int a = 0; a < 3; a++) {
            float l = R[a][0] * x0 + R[a][1] * x1 + R[a][2] * x2 + tv[a];
            g_kp2[(h * KD + 16 + p * 3 + a) * S + s] = l;
            nk += l * l;
        }
    }
    g_kp2[(h * KD + 28) * S + s] = cf * nk;

#pragma unroll
    for (int p = 0; p < 8; p++) {
        float x0 = Ps[864 + h * 24 + p * 3 + 0];
        float x1 = Ps[864 + h * 24 + p * 3 + 1];
        float x2 = Ps[864 + h * 24 + p * 3 + 2];
#pragma unroll
        for (int a = 0; a < 3; a++)
            g_U[(size_t)(h * S + s) * UC + 16 + p * 3 + a] =
                R[a][0] * x0 + R[a][1] * x1 + R[a][2] * x2 + tv[a];
    }
#pragma unroll
    for (int c = 40; c < UC; c++) g_U[(size_t)(h * S + s) * UC + c] = 0.0f;
}

// ---------------- K2: w_pair — R13-exact (warp-private, barrier-free) ------
__global__ void __launch_bounds__(128) k_wpair(const float* __restrict__ pair,
                                               const float* __restrict__ Wb) {
    extern __shared__ float sm[];
    float4* buf = (float4*)sm;                 // [4 warps][2 stages][16 j][32 q4]
    float*  swb = sm + 4 * 2 * 16 * 32 * 4;    // [12][132]
    const int i = blockIdx.x;
    const int t = threadIdx.x;
    const int lane = t & 31, w = t >> 5;

    for (int x = t; x < NH * CP; x += 128) swb[(x >> 7) * 132 + (x & 127)] = Wb[x];

    float4* wbuf = buf + w * 1024;             // this warp's 2-stage ring
    const float4* gp = (const float4*)pair + ((size_t)i * S + w * 16) * 32;

#pragma unroll
    for (int r = 0; r < 16; r++) {
        int q = lane;
        CP16(sptr(&wbuf[r * 32 + ((q + (r >> 1)) & 31)]), gp + r * 32 + q);
    }
    CP_COMMIT();
    __syncthreads();                           // Wb visible to all warps

    const int jq = lane >> 2, hq = lane & 3;
    const int jl = jq * 2;
    const int h0 = hq * 3;

    for (int c = 0; c < 12; c++) {
        float4* cur = wbuf + (c & 1) * 512;
        if (c + 1 < 12) {
            float4* nxt = wbuf + ((c + 1) & 1) * 512;
            const float4* gsrc = gp + (size_t)(c + 1) * 64 * 32;
#pragma unroll
            for (int r = 0; r < 16; r++) {
                int q = lane;
                CP16(sptr(&nxt[r * 32 + ((q + (r >> 1)) & 31)]), gsrc + r * 32 + q);
            }
        }
        CP_COMMIT();
        CP_WAIT1();                            // per-warp wait, no bar.sync

        u64 accA[3][2] = {}, accB[3][2] = {};
#pragma unroll
        for (int q = 0; q < 32; q++) {
            int slot = (q + (jl >> 1)) & 31;
            float4 pa = cur[jl * 32 + slot];
            float4 pb = cur[(jl + 1) * 32 + slot];
            u64 a0 = pk(pa.x, pa.y), a1 = pk(pa.z, pa.w);
            u64 b0 = pk(pb.x, pb.y), b1 = pk(pb.z, pb.w);
#pragma unroll
            for (int r = 0; r < 3; r++) {
                float4 wv = *(const float4*)&swb[(h0 + r) * 132 + q * 4];
                u64 w0 = pk(wv.x, wv.y), w1 = pk(wv.z, wv.w);
                fma2(accA[r][0], a0, w0); fma2(accA[r][1], a1, w1);
                fma2(accB[r][0], b0, w0); fma2(accB[r][1], b1, w1);
            }
        }
        int jg = c * 64 + w * 16 + jl;
#pragma unroll
        for (int r = 0; r < 3; r++) {
            float2 xa = upk(accA[r][0]), ya = upk(accA[r][1]);
            float2 xb = upk(accB[r][0]), yb = upk(accB[r][1]);
            float* wrow = g_wpair + ((size_t)(h0 + r) * S + i) * S + jg;
            wrow[0] = xa.x + xa.y + ya.x + ya.y;
            wrow[1] = xb.x + xb.y + yb.x + yb.y;
        }
    }
}

// ---------------- K3: logits + softmax + fused block column-sums -----------
__global__ void __launch_bounds__(512, 2) k_soft() {
    extern __shared__ float sm[];
    float* ks = sm;                        // [29][768]; reused as stage [16][768]
    float* sq = sm + KD * S;               // [16 rows][32]
    const int h  = blockIdx.y;
    const int i0 = blockIdx.x * 16;
    const int t  = threadIdx.x;

    for (int x = t; x < KD * S; x += 512) ks[x] = g_kp2[(size_t)h * KD * S + x];
    sq[t] = g_qp2[(size_t)(h * S + i0 + (t >> 5)) * 32 + (t & 31)];
    __syncthreads();

    const int w = t >> 5, lane = t & 31;
    const int i = i0 + w;
    const float* wp = g_wpair + ((size_t)h * S + i) * S + lane * 4;

    u64 lo[6], hi[6];
#pragma unroll
    for (int b = 0; b < 6; b++) {
        float4 v = *(const float4*)&wp[b * 128];
        lo[b] = pk(v.x, v.y); hi[b] = pk(v.z, v.w);
    }
#pragma unroll
    for (int e = 0; e < KD; e++) {
        float qe = sq[w * 32 + e];
        u64 q2 = pk(qe, qe);
        const float* kr = ks + e * S + lane * 4;
#pragma unroll
        for (int b = 0; b < 6; b++) {
            float4 kk = *(const float4*)&kr[b * 128];
            fma2(lo[b], q2, pk(kk.x, kk.y));
            fma2(hi[b], q2, pk(kk.z, kk.w));
        }
    }

    float4 l4[6];
    float m = -1e30f;
#pragma unroll
    for (int b = 0; b < 6; b++) {
        float2 a = upk(lo[b]), c = upk(hi[b]);
        l4[b] = make_float4(a.x, a.y, c.x, c.y);
        m = fmaxf(m, fmaxf(fmaxf(a.x, a.y), fmaxf(c.x, c.y)));
    }
#pragma unroll
    for (int o = 16; o > 0; o >>= 1) m = fmaxf(m, __shfl_xor_sync(0xffffffffu, m, o));
    float sum = 0.0f;
#pragma unroll
    for (int b = 0; b < 6; b++) {
        l4[b].x = __expf(l4[b].x - m); l4[b].y = __expf(l4[b].y - m);
        l4[b].z = __expf(l4[b].z - m); l4[b].w = __expf(l4[b].w - m);
        sum += (l4[b].x + l4[b].y) + (l4[b].z + l4[b].w);
    }
#pragma unroll
    for (int o = 16; o > 0; o >>= 1) sum += __shfl_xor_sync(0xffffffffu, sum, o);
    float inv = 1.0f / sum;
    float4 o4[6];
#pragma unroll
    for (int b = 0; b < 6; b++)
        o4[b] = make_float4(l4[b].x * inv, l4[b].y * inv, l4[b].z * inv, l4[b].w * inv);
    float* ap = g_a + ((size_t)h * S + i) * S + lane * 4;
#pragma unroll
    for (int b = 0; b < 6; b++) *(float4*)&ap[b * 128] = o4[b];

    // fused column partial sums (deterministic; reuse ks as [16][768] stage)
    __syncthreads();
    float* stage = ks;
#pragma unroll
    for (int b = 0; b < 6; b++)
        *(float4*)&stage[w * S + lane * 4 + b * 128] = o4[b];
    __syncthreads();
    for (int x = t; x < S; x += 512) {
        float s = 0.f;
#pragma unroll
        for (int r = 0; r < 16; r++) s += stage[r * S + x];
        g_asp[((size_t)h * 48 + blockIdx.x) * S + x] = s;
    }
}

// ---------------- K4: finish column sums (more blocks for latency) ---------
__global__ void k_asum2() {
    int X = blockIdx.x * 64 + threadIdx.x;       // 0 .. NH*S-1
    int h = X / S, j = X - h * S;
    float s = 0.f;
#pragma unroll 8
    for (int b = 0; b < 48; b++) s += g_asp[((size_t)h * 48 + b) * S + j];
    g_asumT[j * NH + h] = s;
}

// ---------------- K5: o_combined = a @ U + fused inverse-frame scatter -----
__global__ void __launch_bounds__(256) k_av(const float* __restrict__ rot,
                                            const float* __restrict__ trans) {
    extern __shared__ float sm[];
    float* sa = sm;                            // [2][32][132]
    float* su = sm + 2 * 32 * 132;             // [2][128][48]
    const int h  = blockIdx.y;
    const int i0 = blockIdx.x * 32;
    const int t  = threadIdx.x;
    const int i  = t & 31, c0 = (t >> 5) * 6;
    u64 acc[3] = {};

    const float4* ga = (const float4*)g_a;
    const float4* gu = (const float4*)g_U + (size_t)h * S * 12;

#pragma unroll
    for (int r = 0; r < 4; r++) {
        int idx = t + 256 * r;
        int ii = idx >> 5, j4 = idx & 31;
        CP16(sptr(&((float4*)sa)[ii * 33 + j4]),
             ga + ((size_t)h * S + i0 + ii) * (S / 4) + j4);
    }
#pragma unroll
    for (int r = 0; r < 6; r++) {
        int idx = t + 256 * r;
        CP16(sptr(&((float4*)su)[idx]), gu + idx);
    }
    CP_COMMIT();

    for (int c = 0; c < 6; c++) {
        float* sac = sa + (c & 1) * 32 * 132;
        float* suc = su + (c & 1) * 128 * 48;
        if (c + 1 < 6) {
            float* san = sa + ((c + 1) & 1) * 32 * 132;
            float* sun = su + ((c + 1) & 1) * 128 * 48;
            int jt4 = (c + 1) * 32;
#pragma unroll
            for (int r = 0; r < 4; r++) {
                int idx = t + 256 * r;
                int ii = idx >> 5, j4 = idx & 31;
                CP16(sptr(&((float4*)san)[ii * 33 + j4]),
                     ga + ((size_t)h * S + i0 + ii) * (S / 4) + jt4 + j4);
            }
            const float4* gun = gu + (c + 1) * 128 * 12;
#pragma unroll
            for (int r = 0; r < 6; r++) {
                int idx = t + 256 * r;
                CP16(sptr(&((float4*)sun)[idx]), gun + idx);
            }
        }
        CP_COMMIT();
        CP_WAIT1();
        __syncthreads();

#pragma unroll 4
        for (int j = 0; j < 128; j++) {
            float av = sac[i * 132 + j];
            u64 p = pk(av, av);
            const u64* uu = (const u64*)&suc[j * UC + c0];
            fma2(acc[0], p, uu[0]); fma2(acc[1], p, uu[1]); fma2(acc[2], p, uu[2]);
        }
        __syncthreads();
    }

    // stage oc into smem [32][49] then fused inverse-frame scatter
    float* soc = sm;
    __syncthreads();
    {
        float2 v0 = upk(acc[0]), v1 = upk(acc[1]), v2 = upk(acc[2]);
        float* d = soc + i * 49 + c0;
        d[0] = v0.x; d[1] = v0.y; d[2] = v1.x; d[3] = v1.y; d[4] = v2.x; d[5] = v2.y;
    }
    __syncthreads();

    if (t < 32) {
        int s = i0 + t;
        const float* oc = soc + t * 49;
        float* f = g_feat + (size_t)s * FEAT;
#pragma unroll
        for (int e = 0; e < EMB; e++) f[h * EMB + e] = oc[e];

        float R[3][3], tv[3];
#pragma unroll
        for (int a = 0; a < 3; a++) {
            tv[a] = trans[s * 3 + a];
#pragma unroll
            for (int b = 0; b < 3; b++) R[a][b] = rot[s * 9 + a * 3 + b];
        }
#pragma unroll
        for (int p = 0; p < 8; p++) {
            float x0 = oc[16 + p * 3 + 0] - tv[0];
            float x1 = oc[16 + p * 3 + 1] - tv[1];
            float x2 = oc[16 + p * 3 + 2] - tv[2];
            float og[3];
#pragma unroll
            for (int a = 0; a < 3; a++) og[a] = R[0][a] * x0 + R[1][a] * x1 + R[2][a] * x2;
#pragma unroll
            for (int a = 0; a < 3; a++) f[1728 + p * 36 + h * 3 + a] = og[a];
            f[2016 + p * 12 + h] = sqrtf(og[0] * og[0] + og[1] * og[1] + og[2] * og[2]);
        }
    }
}

// ---------------- K7: o_pair — warp-private rings, barrier-free main loop --
// warp w owns k-rows [c*64 + w*8, +8); thread (w, c4) owns channels c4*4..+4.
__global__ void __launch_bounds__(256) k_opair(const float* __restrict__ pair) {
    extern __shared__ float sm[];
    float4* ring  = (float4*)sm;               // [8 warps][2 stages][8 k][32 c4]
    float4* aring = (float4*)sm + 8 * 512;     // [8 warps][2 stages][24]
    const int i = blockIdx.x;
    const int t = threadIdx.x;
    const int lane = t & 31, w = t >> 5;
    const int c4 = lane;

    float4* wring  = ring + w * 512;
    float4* waring = aring + w * 48;

    const float4* gp = (const float4*)pair + ((size_t)i * S + w * 8) * 32;
    const float4* gs = (const float4*)g_asumT + w * 24;   // row k = 3 float4

    // prefetch chunk 0
#pragma unroll
    for (int r = 0; r < 8; r++)
        CP16(sptr(&wring[r * 32 + lane]), gp + r * 32 + lane);
    if (lane < 24) CP16(sptr(&waring[lane]), gs + lane);
    CP_COMMIT();

    u64 acc[4][6] = {};
    for (int c = 0; c < 12; c++) {
        float4* cur = wring + (c & 1) * 256;
        const float* scur = (const float*)(waring + (c & 1) * 24);
        if (c + 1 < 12) {
            float4* nxt = wring + ((c + 1) & 1) * 256;
            const float4* gsrc = gp + (size_t)(c + 1) * 64 * 32;
#pragma unroll
            for (int r = 0; r < 8; r++)
                CP16(sptr(&nxt[r * 32 + lane]), gsrc + r * 32 + lane);
            if (lane < 24)
                CP16(sptr(&waring[((c + 1) & 1) * 24 + lane]),
                     gs + (size_t)(c + 1) * 192 + lane);
        }
        CP_COMMIT();
        CP_WAIT1();                            // per-warp; no bar.sync

#pragma unroll
        for (int r = 0; r < 8; r++) {
            float4 p = cur[r * 32 + c4];
            const float4* au4 = (const float4*)&scur[r * 12];   // 3x LDS.128 bcast
            float4 A0 = au4[0], A1 = au4[1], A2 = au4[2];
            u64 a0 = pk(A0.x, A0.y), a1 = pk(A0.z, A0.w);
            u64 a2 = pk(A1.x, A1.y), a3 = pk(A1.z, A1.w);
            u64 a4 = pk(A2.x, A2.y), a5 = pk(A2.z, A2.w);
            u64 px = pk(p.x, p.x), py = pk(p.y, p.y), pz = pk(p.z, p.z), pw = pk(p.w, p.w);
            fma2(acc[0][0], px, a0); fma2(acc[0][1], px, a1); fma2(acc[0][2], px, a2);
            fma2(acc[0][3], px, a3); fma2(acc[0][4], px, a4); fma2(acc[0][5], px, a5);
            fma2(acc[1][0], py, a0); fma2(acc[1][1], py, a1); fma2(acc[1][2], py, a2);
            fma2(acc[1][3], py, a3); fma2(acc[1][4], py, a4); fma2(acc[1][5], py, a5);
            fma2(acc[2][0], pz, a0); fma2(acc[2][1], pz, a1); fma2(acc[2][2], pz, a2);
            fma2(acc[2][3], pz, a3); fma2(acc[2][4], pz, a4); fma2(acc[2][5], pz, a5);
            fma2(acc[3][0], pw, a0); fma2(acc[3][1], pw, a1); fma2(acc[3][2], pw, a2);
            fma2(acc[3][3], pw, a3); fma2(acc[3][4], pw, a4); fma2(acc[3][5], pw, a5);
        }
    }
    __syncthreads();                            // rings free; epilogue staging

    float rv[48];
#pragma unroll
    for (int cc = 0; cc < 4; cc++)
#pragma unroll
        for (int hp = 0; hp < 6; hp++) {
            float2 v = upk(acc[cc][hp]);
            rv[cc * 12 + 2 * hp]     = v.x;
            rv[cc * 12 + 2 * hp + 1] = v.y;
        }

    float* red = sm;
    const int kk = w;
#pragma unroll
    for (int step = 4; step >= 1; step >>= 1) {
        if (kk >= step && kk < 2 * step) {
            float* d = red + ((kk - step) * 32 + c4) * 48;
#pragma unroll
            for (int x = 0; x < 48; x += 4)
                *(float4*)&d[x] = make_float4(rv[x], rv[x + 1], rv[x + 2], rv[x + 3]);
        }
        __syncthreads();
        if (kk < step) {
            const float* d = red + (kk * 32 + c4) * 48;
#pragma unroll
            for (int x = 0; x < 48; x++) rv[x] += d[x];
        }
        __syncthreads();
    }
    if (kk == 0) {
        float* f = g_feat + (size_t)i * FEAT + 192 + c4 * 4;
#pragma unroll
        for (int hh = 0; hh < 12; hh++)
            *(float4*)&f[hh * CP] =
                make_float4(rv[hh], rv[12 + hh], rv[24 + hh], rv[36 + hh]);
    }
}

// ---------------- K8: out partials = feat @ Wo^T (split-K=2, reg-db) -------
__global__ void k_out(const float* __restrict__ Wo) {
    __shared__ float As[32 * 68];
    __shared__ float Bs[32 * 68];
    const int n0 = blockIdx.x * 64, m0 = blockIdx.y * 64, z = blockIdx.z;
    const int t  = threadIdx.x;
    const int i0 = (t & 15) * 4, j0 = (t >> 4) * 4;
    const int kbase = z * (FEAT / 2);

    int aoff[8], boff[8], aidx[8], bidx[8];
#pragma unroll
    for (int r = 0; r < 8; r++) {
        int idx = t + 256 * r;
        int i = idx >> 5, k = idx & 31;
        aoff[r] = (m0 + i) * FEAT + kbase + k;
        aidx[r] = k * 68 + i;
        boff[r] = (n0 + i) * FEAT + kbase + k;
        bidx[r] = k * 68 + i;
    }
    u64 acc[4][2] = {};
    float ra[8], rb[8];
#pragma unroll
    for (int r = 0; r < 8; r++) { ra[r] = g_feat[aoff[r]]; rb[r] = Wo[boff[r]]; }

    for (int kt = 0; kt < FEAT / 2; kt += 32) {
#pragma unroll
        for (int r = 0; r < 8; r++) { As[aidx[r]] = ra[r]; Bs[bidx[r]] = rb[r]; }
        __syncthreads();
        if (kt + 32 < FEAT / 2) {
#pragma unroll
            for (int r = 0; r < 8; r++) {
                ra[r] = g_feat[aoff[r] + kt + 32];
                rb[r] = Wo[boff[r] + kt + 32];
            }
        }
#pragma unroll
        for (int k = 0; k < 32; k++) {
            float4 a4 = *(const float4*)&As[k * 68 + i0];
            float4 b4 = *(const float4*)&Bs[k * 68 + j0];
            u64 bxy = pk(b4.x, b4.y), bzw = pk(b4.z, b4.w);
            float av[4] = {a4.x, a4.y, a4.z, a4.w};
#pragma unroll
            for (int ii = 0; ii < 4; ii++) {
                u64 aa = pk(av[ii], av[ii]);
                fma2(acc[ii][0], aa, bxy);
                fma2(acc[ii][1], aa, bzw);
            }
        }
        __syncthreads();
    }
#pragma unroll
    for (int ii = 0; ii < 4; ii++) {
        float2 lo = upk(acc[ii][0]), hi = upk(acc[ii][1]);
        float* o = &g_out2[(size_t)z * S * CS + (m0 + i0 + ii) * CS + n0 + j0];
        o[0] = lo.x; o[1] = lo.y; o[2] = hi.x; o[3] = hi.y;
    }
}

// ---------------- K9: combine split-K partials + bias ----------------------
__global__ void k_bias(const float* __restrict__ bo, float* __restrict__ out) {
    int x = blockIdx.x * 256 + threadIdx.x;
    float4 a = ((const float4*)g_out2)[x];
    float4 b = ((const float4*)g_out2)[S * CS / 4 + x];
    int n = (x * 4) % CS;
    float4 bb = *(const float4*)&bo[n];
    ((float4*)out)[x] = make_float4(a.x + b.x + bb.x, a.y + b.y + bb.y,
                                    a.z + b.z + bb.z, a.w + b.w + bb.w);
}

// ---------------------------------------------------------------------------
extern "C" void kernel_launch(void* const* d_in, const int* in_sizes, int n_in,
                              void* d_out, int out_size) {
    const float* single = (const float*)d_in[0];
    const float* pair   = (const float*)d_in[1];
    const float* rot    = (const float*)d_in[2];
    const float* trans  = (const float*)d_in[3];
    const float* Wq     = (const float*)d_in[4];
    const float* Wk     = (const float*)d_in[5];
    const float* Wv     = (const float*)d_in[6];
    const float* Wqp    = (const float*)d_in[7];
    const float* Wkp    = (const float*)d_in[8];
    const float* Wvp    = (const float*)d_in[9];
    const float* Wb     = (const float*)d_in[10];
    const float* Wo     = (const float*)d_in[11];
    const float* bo     = (const float*)d_in[12];
    const float* gamma  = (const float*)d_in[13];
    float* out = (float*)d_out;

    const int SMEM_WPAIR = 4 * 2 * 16 * 32 * 16 + 12 * 132 * 4; // 71872
    const int SMEM_SOFT  = KD * S * 4 + 16 * 32 * 4;            // 91136
    const int SMEM_AV    = 2 * 32 * 132 * 4 + 2 * 128 * 48 * 4; // 82944
    const int SMEM_OPAIR = 8 * 512 * 16 + 8 * 48 * 16;          // 71680
    cudaFuncSetAttribute(k_wpair, cudaFuncAttributeMaxDynamicSharedMemorySize, SMEM_WPAIR);
    cudaFuncSetAttribute(k_soft,  cudaFuncAttributeMaxDynamicSharedMemorySize, SMEM_SOFT);
    cudaFuncSetAttribute(k_av,    cudaFuncAttributeMaxDynamicSharedMemorySize, SMEM_AV);
    cudaFuncSetAttribute(k_opair, cudaFuncAttributeMaxDynamicSharedMemorySize, SMEM_OPAIR);

    k_proj   <<<dim3(NPROJ / 64, S / 32), 256>>>(single, Wq, Wk, Wv, Wqp, Wkp, Wvp);
    k_frames <<<(NH * S + 255) / 256, 256>>>(rot, trans, gamma);
    k_wpair  <<<S, 128, SMEM_WPAIR>>>(pair, Wb);
    k_soft   <<<dim3(S / 16, NH), 512, SMEM_SOFT>>>();
    k_asum2  <<<(NH * S) / 64, 64>>>();
    k_av     <<<dim3(S / 32, NH), 256, SMEM_AV>>>(rot, trans);
    k_opair  <<<S, 256, SMEM_OPAIR>>>(pair);
    k_out    <<<dim3(CS / 64, S / 64, 2), 256>>>(Wo);
    k_bias   <<<(S * CS / 4) / 256, 256>>>(bo, out);
}

// round 16
// speedup vs baseline: 1.2433x; 1.0947x over previous
#include <cuda_runtime.h>
#include <math.h>

#define S     768
#define CS    384
#define CP    128
#define EMB   16
#define NH    12
#define NPROJ 1152          // 3*H*E + 2*H*PQ*3 + H*PV*3
#define FEAT  2112          // H*(E + CP + PV*3 + PV)
#define UC    48            // padded combined [v(16) | lvp(24) | zero-pad(8)]
#define KD    29            // augmented K' dims

typedef unsigned long long u64;

// ---- packed fp32x2 FMA (FFMA2 — PTX-only on sm_103a) --------------------
__device__ __forceinline__ u64 pk(float x, float y) {
    u64 r; asm("mov.b64 %0, {%1,%2};" : "=l"(r) : "f"(x), "f"(y)); return r;
}
__device__ __forceinline__ float2 upk(u64 v) {
    float2 r; asm("mov.b64 {%0,%1}, %2;" : "=f"(r.x), "=f"(r.y) : "l"(v)); return r;
}
__device__ __forceinline__ void fma2(u64& d, u64 a, u64 b) {
    asm("fma.rn.f32x2 %0, %1, %2, %0;" : "+l"(d) : "l"(a), "l"(b));
}
// ---- cp.async helpers -----------------------------------------------------
__device__ __forceinline__ unsigned sptr(const void* p) {
    return (unsigned)__cvta_generic_to_shared(p);
}
#define CP16(dst, src) asm volatile("cp.async.cg.shared.global [%0], [%1], 16;" :: "r"(dst), "l"(src))
#define CP_COMMIT()    asm volatile("cp.async.commit_group;")
#define CP_WAIT1()     asm volatile("cp.async.wait_group 1;" ::: "memory")
// ---- tf32 mma.sync m16n8k8 -------------------------------------------------
#define MMA8(D, A0, A1, A2, A3, B0, B1) \
    asm volatile("mma.sync.aligned.m16n8k8.row.col.f32.tf32.tf32.f32 " \
        "{%0,%1,%2,%3}, {%4,%5,%6,%7}, {%8,%9}, {%0,%1,%2,%3};" \
        : "+f"(D[0]), "+f"(D[1]), "+f"(D[2]), "+f"(D[3]) \
        : "r"(A0), "r"(A1), "r"(A2), "r"(A3), "r"(B0), "r"(B1))

// ---------------- scratch (device globals) --------------------------------
__device__ float g_P[S * NPROJ];
__device__ float g_qp2[NH * S * 32];
__device__ float g_kp2[NH * KD * S];
__device__ float g_U[NH * S * UC];
__device__ float g_wpair[NH * S * S];
__device__ float g_a[NH * S * S];
__device__ float g_asp[NH * 48 * S];      // per-block column partials
__device__ float g_asumT[S * NH];
__device__ float g_feat[S * FEAT];
__device__ float g_out2[2 * S * CS];

// ---------------- K0: filler (positions k_wpair at launch #4 for ncu) ------
__global__ void k_pre() {
    int x = blockIdx.x * 256 + threadIdx.x;
    if (x < S * NH) g_asumT[x] = 0.0f;       // overwritten by k_asum2 later
}

// ---------------- K1: packed projection GEMM (reg double-buffered) --------
__global__ void k_proj(const float* __restrict__ single,
                       const float* __restrict__ Wq, const float* __restrict__ Wk,
                       const float* __restrict__ Wv, const float* __restrict__ Wqp,
                       const float* __restrict__ Wkp, const float* __restrict__ Wvp) {
    __shared__ float As[32 * 36];
    __shared__ float Bs[32 * 68];
    const int n0 = blockIdx.x * 64, m0 = blockIdx.y * 32;
    const int t  = threadIdx.x;
    const int i0 = (t & 15) * 2, j0 = (t >> 4) * 4;

    const float* asrc[4]; int aidx[4];
#pragma unroll
    for (int r = 0; r < 4; r++) {
        int idx = t + 256 * r;
        int i = idx >> 5, k = idx & 31;
        asrc[r] = single + (m0 + i) * CS + k;
        aidx[r] = k * 36 + i;
    }
    const float* bsrc[8]; int bidx[8];
#pragma unroll
    for (int r = 0; r < 8; r++) {
        int idx = t + 256 * r;
        int j = idx >> 5, k = idx & 31;
        int n = n0 + j;
        const float* row;
        if (n < 192)      row = Wq  + n * CS;
        else if (n < 384) row = Wk  + (n - 192) * CS;
        else if (n < 576) row = Wv  + (n - 384) * CS;
        else if (n < 720) row = Wqp + (n - 576) * CS;
        else if (n < 864) row = Wkp + (n - 720) * CS;
        else              row = Wvp + (n - 864) * CS;
        bsrc[r] = row + k;
        bidx[r] = k * 68 + j;
    }
    u64 acc[2][2] = {};
    float ra[4], rb[8];
#pragma unroll
    for (int r = 0; r < 4; r++) ra[r] = asrc[r][0];
#pragma unroll
    for (int r = 0; r < 8; r++) rb[r] = bsrc[r][0];

    for (int kt = 0; kt < CS; kt += 32) {
#pragma unroll
        for (int r = 0; r < 4; r++) As[aidx[r]] = ra[r];
#pragma unroll
        for (int r = 0; r < 8; r++) Bs[bidx[r]] = rb[r];
        __syncthreads();
        if (kt + 32 < CS) {
#pragma unroll
            for (int r = 0; r < 4; r++) ra[r] = asrc[r][kt + 32];
#pragma unroll
            for (int r = 0; r < 8; r++) rb[r] = bsrc[r][kt + 32];
        }
#pragma unroll
        for (int k = 0; k < 32; k++) {
            float2 a2 = *(const float2*)&As[k * 36 + i0];
            float4 b4 = *(const float4*)&Bs[k * 68 + j0];
            u64 bxy = pk(b4.x, b4.y), bzw = pk(b4.z, b4.w);
            u64 ax = pk(a2.x, a2.x), ay = pk(a2.y, a2.y);
            fma2(acc[0][0], ax, bxy); fma2(acc[0][1], ax, bzw);
            fma2(acc[1][0], ay, bxy); fma2(acc[1][1], ay, bzw);
        }
        __syncthreads();
    }
#pragma unroll
    for (int ii = 0; ii < 2; ii++) {
        float2 lo = upk(acc[ii][0]), hi = upk(acc[ii][1]);
        float* o = &g_P[(m0 + i0 + ii) * NPROJ + n0 + j0];
        o[0] = lo.x; o[1] = lo.y; o[2] = hi.x; o[3] = hi.y;
    }
}

// ---------------- K1b: frame apply + augmented Q'/K' build ----------------
__global__ void k_frames(const float* __restrict__ rot, const float* __restrict__ trans,
                         const float* __restrict__ gamma) {
    int idx = blockIdx.x * blockDim.x + threadIdx.x;
    if (idx >= NH * S) return;
    int h = idx / S, s = idx % S;

    float g  = gamma[h];
    float sp = (g > 20.f) ? g : log1pf(expf(g));
    float cf = -0.11785113f * sp;

    float R[3][3], tv[3];
#pragma unroll
    for (int a = 0; a < 3; a++) {
        tv[a] = trans[s * 3 + a];
#pragma unroll
        for (int b = 0; b < 3; b++) R[a][b] = rot[s * 9 + a * 3 + b];
    }
    const float* Ps = g_P + (size_t)s * NPROJ;
    float* qp2 = g_qp2 + (size_t)(h * S + s) * 32;

#pragma unroll
    for (int e = 0; e < EMB; e++) {
        qp2[e] = 0.25f * Ps[h * EMB + e];
        g_kp2[(h * KD + e) * S + s]        = Ps[192 + h * EMB + e];
        g_U[(size_t)(h * S + s) * UC + e]  = Ps[384 + h * EMB + e];
    }
    float m2cf = -2.0f * cf;
#pragma unroll
    for (int p = 0; p < 4; p++) {
        float x0 = Ps[576 + h * 12 + p * 3 + 0];
        float x1 = Ps[576 + h * 12 + p * 3 + 1];
        float x2 = Ps[576 + h * 12 + p * 3 + 2];
#pragma unroll
        for (int a = 0; a < 3; a++) {
            float l = R[a][0] * x0 + R[a][1] * x1 + R[a][2] * x2 + tv[a];
            qp2[16 + p * 3 + a] = m2cf * l;
        }
    }
    qp2[28] = 1.0f; qp2[29] = 0.0f; qp2[30] = 0.0f; qp2[31] = 0.0f;

    float nk = 0.0f;
#pragma unroll
    for (int p = 0; p < 4; p++) {
        float x0 = Ps[720 + h * 12 + p * 3 + 0];
        float x1 = Ps[720 + h * 12 + p * 3 + 1];
        float x2 = Ps[720 + h * 12 + p * 3 + 2];
#pragma unroll
        for (int a = 0; a < 3; a++) {
            float l = R[a][0] * x0 + R[a][1] * x1 + R[a][2] * x2 + tv[a];
            g_kp2[(h * KD + 16 + p * 3 + a) * S + s] = l;
            nk += l * l;
        }
    }
    g_kp2[(h * KD + 28) * S + s] = cf * nk;

#pragma unroll
    for (int p = 0; p < 8; p++) {
        float x0 = Ps[864 + h * 24 + p * 3 + 0];
        float x1 = Ps[864 + h * 24 + p * 3 + 1];
        float x2 = Ps[864 + h * 24 + p * 3 + 2];
#pragma unroll
        for (int a = 0; a < 3; a++)
            g_U[(size_t)(h * S + s) * UC + 16 + p * 3 + a] =
                R[a][0] * x0 + R[a][1] * x1 + R[a][2] * x2 + tv[a];
    }
#pragma unroll
    for (int c = 40; c < UC; c++) g_U[(size_t)(h * S + s) * UC + c] = 0.0f;
}

// ---------------- K2: w_pair — tf32 mma.sync, warp-private rings ------------
// Per block: one i. Warp w handles j-tiles {w, w+4, ..., w+44} (16 j each).
// GEMM per tile: [16 j] x [128 k] x [16 h-padded], m16n8k8 tf32.
__global__ void __launch_bounds__(128) k_wpair(const float* __restrict__ pair,
                                               const float* __restrict__ Wb) {
    extern __shared__ float sm[];
    float4* buf = (float4*)sm;                   // [4 warps][2 stages][512 f4]
    float*  swb = sm + 4 * 2 * 512 * 4;          // [16][132] tf32 bits (rows 12-15 zero)
    const int i = blockIdx.x;
    const int t = threadIdx.x;
    const int lane = t & 31, w = t >> 5;

    for (int x = t; x < 16 * 132; x += 128) {
        int row = x / 132, col = x - row * 132;
        float v = (row < NH && col < CP) ? Wb[row * CP + col] : 0.0f;
        unsigned b; asm("cvt.rna.tf32.f32 %0, %1;" : "=r"(b) : "f"(v));
        ((unsigned*)swb)[x] = b;
    }

    float4* wring = buf + w * 1024;              // 2 stages x 512 float4
    const float4* gp = (const float4*)pair + (size_t)i * S * 32;

    // prefetch j-tile w (rows r: rotated float4 columns (lane + r) & 31)
#pragma unroll
    for (int r = 0; r < 16; r++)
        CP16(sptr(&wring[r * 32 + ((lane + r) & 31)]), gp + (w * 16 + r) * 32 + lane);
    CP_COMMIT();
    __syncthreads();                             // swb visible to all warps

    const unsigned* swbu = (const unsigned*)swb;
    const int r0 = lane >> 2, kb = lane & 3;
    const int h0 = 2 * kb;

    for (int c = 0; c < 12; c++) {
        const unsigned* cur = (const unsigned*)(wring + (c & 1) * 512);
        if (c + 1 < 12) {
            float4* nxt = wring + ((c + 1) & 1) * 512;
            int jt = w + 4 * (c + 1);
#pragma unroll
            for (int r = 0; r < 16; r++)
                CP16(sptr(&nxt[r * 32 + ((lane + r) & 31)]), gp + (jt * 16 + r) * 32 + lane);
        }
        CP_COMMIT();
        CP_WAIT1();                              // per-warp wait, no bar.sync

        float d0[4] = {0.f, 0.f, 0.f, 0.f};      // n-tile 0: h 0..7
        float d1[4] = {0.f, 0.f, 0.f, 0.f};      // n-tile 1: h 8..15 (12+ unused)
#pragma unroll
        for (int kc = 0; kc < 16; kc++) {
            int sa = (2 * kc + r0) & 31;         // float4 slot, k-low, row r0
            int sb = (2 * kc + 1 + r0) & 31;     // k-high
            int sc = (2 * kc + r0 + 8) & 31;     // row r0+8
            int sd = (2 * kc + 1 + r0 + 8) & 31;
            unsigned a0 = cur[r0 * 128 + sa * 4 + kb];
            unsigned a1 = cur[(r0 + 8) * 128 + sc * 4 + kb];
            unsigned a2 = cur[r0 * 128 + sb * 4 + kb];
            unsigned a3 = cur[(r0 + 8) * 128 + sd * 4 + kb];
            unsigned b0 = swbu[r0 * 132 + kc * 8 + kb];
            unsigned b1 = swbu[r0 * 132 + kc * 8 + kb + 4];
            unsigned b2 = swbu[(r0 + 8) * 132 + kc * 8 + kb];
            unsigned b3 = swbu[(r0 + 8) * 132 + kc * 8 + kb + 4];
            MMA8(d0, a0, a1, a2, a3, b0, b1);
            MMA8(d1, a0, a1, a2, a3, b2, b3);
        }
        int j = (w + 4 * c) * 16 + r0;
        g_wpair[((size_t)h0 * S + i) * S + j]           = d0[0];
        g_wpair[((size_t)(h0 + 1) * S + i) * S + j]     = d0[1];
        g_wpair[((size_t)h0 * S + i) * S + j + 8]       = d0[2];
        g_wpair[((size_t)(h0 + 1) * S + i) * S + j + 8] = d0[3];
        if (h0 < 4) {                            // h 8..11 only
            g_wpair[((size_t)(8 + h0) * S + i) * S + j]           = d1[0];
            g_wpair[((size_t)(9 + h0) * S + i) * S + j]           = d1[1];
            g_wpair[((size_t)(8 + h0) * S + i) * S + j + 8]       = d1[2];
            g_wpair[((size_t)(9 + h0) * S + i) * S + j + 8]       = d1[3];
        }
    }
}

// ---------------- K3: logits + softmax + fused block column-sums -----------
__global__ void __launch_bounds__(512, 2) k_soft() {
    extern __shared__ float sm[];
    float* ks = sm;                        // [29][768]; reused as stage [16][768]
    float* sq = sm + KD * S;               // [16 rows][32]
    const int h  = blockIdx.y;
    const int i0 = blockIdx.x * 16;
    const int t  = threadIdx.x;

    for (int x = t; x < KD * S; x += 512) ks[x] = g_kp2[(size_t)h * KD * S + x];
    sq[t] = g_qp2[(size_t)(h * S + i0 + (t >> 5)) * 32 + (t & 31)];
    __syncthreads();

    const int w = t >> 5, lane = t & 31;
    const int i = i0 + w;
    const float* wp = g_wpair + ((size_t)h * S + i) * S + lane * 4;

    u64 lo[6], hi[6];
#pragma unroll
    for (int b = 0; b < 6; b++) {
        float4 v = *(const float4*)&wp[b * 128];
        lo[b] = pk(v.x, v.y); hi[b] = pk(v.z, v.w);
    }
#pragma unroll
    for (int e = 0; e < KD; e++) {
        float qe = sq[w * 32 + e];
        u64 q2 = pk(qe, qe);
        const float* kr = ks + e * S + lane * 4;
#pragma unroll
        for (int b = 0; b < 6; b++) {
            float4 kk = *(const float4*)&kr[b * 128];
            fma2(lo[b], q2, pk(kk.x, kk.y));
            fma2(hi[b], q2, pk(kk.z, kk.w));
        }
    }

    float4 l4[6];
    float m = -1e30f;
#pragma unroll
    for (int b = 0; b < 6; b++) {
        float2 a = upk(lo[b]), c = upk(hi[b]);
        l4[b] = make_float4(a.x, a.y, c.x, c.y);
        m = fmaxf(m, fmaxf(fmaxf(a.x, a.y), fmaxf(c.x, c.y)));
    }
#pragma unroll
    for (int o = 16; o > 0; o >>= 1) m = fmaxf(m, __shfl_xor_sync(0xffffffffu, m, o));
    float sum = 0.0f;
#pragma unroll
    for (int b = 0; b < 6; b++) {
        l4[b].x = __expf(l4[b].x - m); l4[b].y = __expf(l4[b].y - m);
        l4[b].z = __expf(l4[b].z - m); l4[b].w = __expf(l4[b].w - m);
        sum += (l4[b].x + l4[b].y) + (l4[b].z + l4[b].w);
    }
#pragma unroll
    for (int o = 16; o > 0; o >>= 1) sum += __shfl_xor_sync(0xffffffffu, sum, o);
    float inv = 1.0f / sum;
    float4 o4[6];
#pragma unroll
    for (int b = 0; b < 6; b++)
        o4[b] = make_float4(l4[b].x * inv, l4[b].y * inv, l4[b].z * inv, l4[b].w * inv);
    float* ap = g_a + ((size_t)h * S + i) * S + lane * 4;
#pragma unroll
    for (int b = 0; b < 6; b++) *(float4*)&ap[b * 128] = o4[b];

    // fused column partial sums (deterministic; reuse ks as [16][768] stage)
    __syncthreads();
    float* stage = ks;
#pragma unroll
    for (int b = 0; b < 6; b++)
        *(float4*)&stage[w * S + lane * 4 + b * 128] = o4[b];
    __syncthreads();
    for (int x = t; x < S; x += 512) {
        float s = 0.f;
#pragma unroll
        for (int r = 0; r < 16; r++) s += stage[r * S + x];
        g_asp[((size_t)h * 48 + blockIdx.x) * S + x] = s;
    }
}

// ---------------- K4: finish column sums ------------------------------------
__global__ void k_asum2() {
    int X = blockIdx.x * 64 + threadIdx.x;       // 0 .. NH*S-1
    int h = X / S, j = X - h * S;
    float s = 0.f;
#pragma unroll 8
    for (int b = 0; b < 48; b++) s += g_asp[((size_t)h * 48 + b) * S + j];
    g_asumT[j * NH + h] = s;
}

// ---------------- K5: o_combined = a @ U + fused inverse-frame scatter -----
__global__ void __launch_bounds__(256) k_av(const float* __restrict__ rot,
                                            const float* __restrict__ trans) {
    extern __shared__ float sm[];
    float* sa = sm;                            // [2][32][132]
    float* su = sm + 2 * 32 * 132;             // [2][128][48]
    const int h  = blockIdx.y;
    const int i0 = blockIdx.x * 32;
    const int t  = threadIdx.x;
    const int i  = t & 31, c0 = (t >> 5) * 6;
    u64 acc[3] = {};

    const float4* ga = (const float4*)g_a;
    const float4* gu = (const float4*)g_U + (size_t)h * S * 12;

#pragma unroll
    for (int r = 0; r < 4; r++) {
        int idx = t + 256 * r;
        int ii = idx >> 5, j4 = idx & 31;
        CP16(sptr(&((float4*)sa)[ii * 33 + j4]),
             ga + ((size_t)h * S + i0 + ii) * (S / 4) + j4);
    }
#pragma unroll
    for (int r = 0; r < 6; r++) {
        int idx = t + 256 * r;
        CP16(sptr(&((float4*)su)[idx]), gu + idx);
    }
    CP_COMMIT();

    for (int c = 0; c < 6; c++) {
        float* sac = sa + (c & 1) * 32 * 132;
        float* suc = su + (c & 1) * 128 * 48;
        if (c + 1 < 6) {
            float* san = sa + ((c + 1) & 1) * 32 * 132;
            float* sun = su + ((c + 1) & 1) * 128 * 48;
            int jt4 = (c + 1) * 32;
#pragma unroll
            for (int r = 0; r < 4; r++) {
                int idx = t + 256 * r;
                int ii = idx >> 5, j4 = idx & 31;
                CP16(sptr(&((float4*)san)[ii * 33 + j4]),
                     ga + ((size_t)h * S + i0 + ii) * (S / 4) + jt4 + j4);
            }
            const float4* gun = gu + (c + 1) * 128 * 12;
#pragma unroll
            for (int r = 0; r < 6; r++) {
                int idx = t + 256 * r;
                CP16(sptr(&((float4*)sun)[idx]), gun + idx);
            }
        }
        CP_COMMIT();
        CP_WAIT1();
        __syncthreads();

#pragma unroll 4
        for (int j = 0; j < 128; j++) {
            float av = sac[i * 132 + j];
            u64 p = pk(av, av);
            const u64* uu = (const u64*)&suc[j * UC + c0];
            fma2(acc[0], p, uu[0]); fma2(acc[1], p, uu[1]); fma2(acc[2], p, uu[2]);
        }
        __syncthreads();
    }

    // stage oc into smem [32][49] then fused inverse-frame scatter
    float* soc = sm;
    __syncthreads();
    {
        float2 v0 = upk(acc[0]), v1 = upk(acc[1]), v2 = upk(acc[2]);
        float* d = soc + i * 49 + c0;
        d[0] = v0.x; d[1] = v0.y; d[2] = v1.x; d[3] = v1.y; d[4] = v2.x; d[5] = v2.y;
    }
    __syncthreads();

    if (t < 32) {
        int s = i0 + t;
        const float* oc = soc + t * 49;
        float* f = g_feat + (size_t)s * FEAT;
#pragma unroll
        for (int e = 0; e < EMB; e++) f[h * EMB + e] = oc[e];

        float R[3][3], tv[3];
#pragma unroll
        for (int a = 0; a < 3; a++) {
            tv[a] = trans[s * 3 + a];
#pragma unroll
            for (int b = 0; b < 3; b++) R[a][b] = rot[s * 9 + a * 3 + b];
        }
#pragma unroll
        for (int p = 0; p < 8; p++) {
            float x0 = oc[16 + p * 3 + 0] - tv[0];
            float x1 = oc[16 + p * 3 + 1] - tv[1];
            float x2 = oc[16 + p * 3 + 2] - tv[2];
            float og[3];
#pragma unroll
            for (int a = 0; a < 3; a++) og[a] = R[0][a] * x0 + R[1][a] * x1 + R[2][a] * x2;
#pragma unroll
            for (int a = 0; a < 3; a++) f[1728 + p * 36 + h * 3 + a] = og[a];
            f[2016 + p * 12 + h] = sqrtf(og[0] * og[0] + og[1] * og[1] + og[2] * og[2]);
        }
    }
}

// ---------------- K7: o_pair — warp-private rings (R15-exact) ---------------
__global__ void __launch_bounds__(256) k_opair(const float* __restrict__ pair) {
    extern __shared__ float sm[];
    float4* ring  = (float4*)sm;               // [8 warps][2 stages][8 k][32 c4]
    float4* aring = (float4*)sm + 8 * 512;     // [8 warps][2 stages][24]
    const int i = blockIdx.x;
    const int t = threadIdx.x;
    const int lane = t & 31, w = t >> 5;
    const int c4 = lane;

    float4* wring  = ring + w * 512;
    float4* waring = aring + w * 48;

    const float4* gp = (const float4*)pair + ((size_t)i * S + w * 8) * 32;
    const float4* gs = (const float4*)g_asumT + w * 24;

#pragma unroll
    for (int r = 0; r < 8; r++)
        CP16(sptr(&wring[r * 32 + lane]), gp + r * 32 + lane);
    if (lane < 24) CP16(sptr(&waring[lane]), gs + lane);
    CP_COMMIT();

    u64 acc[4][6] = {};
    for (int c = 0; c < 12; c++) {
        float4* cur = wring + (c & 1) * 256;
        const float* scur = (const float*)(waring + (c & 1) * 24);
        if (c + 1 < 12) {
            float4* nxt = wring + ((c + 1) & 1) * 256;
            const float4* gsrc = gp + (size_t)(c + 1) * 64 * 32;
#pragma unroll
            for (int r = 0; r < 8; r++)
                CP16(sptr(&nxt[r * 32 + lane]), gsrc + r * 32 + lane);
            if (lane < 24)
                CP16(sptr(&waring[((c + 1) & 1) * 24 + lane]),
                     gs + (size_t)(c + 1) * 192 + lane);
        }
        CP_COMMIT();
        CP_WAIT1();

#pragma unroll
        for (int r = 0; r < 8; r++) {
            float4 p = cur[r * 32 + c4];
            const float4* au4 = (const float4*)&scur[r * 12];
            float4 A0 = au4[0], A1 = au4[1], A2 = au4[2];
            u64 a0 = pk(A0.x, A0.y), a1 = pk(A0.z, A0.w);
            u64 a2 = pk(A1.x, A1.y), a3 = pk(A1.z, A1.w);
            u64 a4 = pk(A2.x, A2.y), a5 = pk(A2.z, A2.w);
            u64 px = pk(p.x, p.x), py = pk(p.y, p.y), pz = pk(p.z, p.z), pw = pk(p.w, p.w);
            fma2(acc[0][0], px, a0); fma2(acc[0][1], px, a1); fma2(acc[0][2], px, a2);
            fma2(acc[0][3], px, a3); fma2(acc[0][4], px, a4); fma2(acc[0][5], px, a5);
            fma2(acc[1][0], py, a0); fma2(acc[1][1], py, a1); fma2(acc[1][2], py, a2);
            fma2(acc[1][3], py, a3); fma2(acc[1][4], py, a4); fma2(acc[1][5], py, a5);
            fma2(acc[2][0], pz, a0); fma2(acc[2][1], pz, a1); fma2(acc[2][2], pz, a2);
            fma2(acc[2][3], pz, a3); fma2(acc[2][4], pz, a4); fma2(acc[2][5], pz, a5);
            fma2(acc[3][0], pw, a0); fma2(acc[3][1], pw, a1); fma2(acc[3][2], pw, a2);
            fma2(acc[3][3], pw, a3); fma2(acc[3][4], pw, a4); fma2(acc[3][5], pw, a5);
        }
    }
    __syncthreads();

    float rv[48];
#pragma unroll
    for (int cc = 0; cc < 4; cc++)
#pragma unroll
        for (int hp = 0; hp < 6; hp++) {
            float2 v = upk(acc[cc][hp]);
            rv[cc * 12 + 2 * hp]     = v.x;
            rv[cc * 12 + 2 * hp + 1] = v.y;
        }

    float* red = sm;
    const int kk = w;
#pragma unroll
    for (int step = 4; step >= 1; step >>= 1) {
        if (kk >= step && kk < 2 * step) {
            float* d = red + ((kk - step) * 32 + c4) * 48;
#pragma unroll
            for (int x = 0; x < 48; x += 4)
                *(float4*)&d[x] = make_float4(rv[x], rv[x + 1], rv[x + 2], rv[x + 3]);
        }
        __syncthreads();
        if (kk < step) {
            const float* d = red + (kk * 32 + c4) * 48;
#pragma unroll
            for (int x = 0; x < 48; x++) rv[x] += d[x];
        }
        __syncthreads();
    }
    if (kk == 0) {
        float* f = g_feat + (size_t)i * FEAT + 192 + c4 * 4;
#pragma unroll
        for (int hh = 0; hh < 12; hh++)
            *(float4*)&f[hh * CP] =
                make_float4(rv[hh], rv[12 + hh], rv[24 + hh], rv[36 + hh]);
    }
}

// ---------------- K8: out partials = feat @ Wo^T (split-K=2, reg-db) -------
__global__ void k_out(const float* __restrict__ Wo) {
    __shared__ float As[32 * 68];
    __shared__ float Bs[32 * 68];
    const int n0 = blockIdx.x * 64, m0 = blockIdx.y * 64, z = blockIdx.z;
    const int t  = threadIdx.x;
    const int i0 = (t & 15) * 4, j0 = (t >> 4) * 4;
    const int kbase = z * (FEAT / 2);

    int aoff[8], boff[8], aidx[8], bidx[8];
#pragma unroll
    for (int r = 0; r < 8; r++) {
        int idx = t + 256 * r;
        int i = idx >> 5, k = idx & 31;
        aoff[r] = (m0 + i) * FEAT + kbase + k;
        aidx[r] = k * 68 + i;
        boff[r] = (n0 + i) * FEAT + kbase + k;
        bidx[r] = k * 68 + i;
    }
    u64 acc[4][2] = {};
    float ra[8], rb[8];
#pragma unroll
    for (int r = 0; r < 8; r++) { ra[r] = g_feat[aoff[r]]; rb[r] = Wo[boff[r]]; }

    for (int kt = 0; kt < FEAT / 2; kt += 32) {
#pragma unroll
        for (int r = 0; r < 8; r++) { As[aidx[r]] = ra[r]; Bs[bidx[r]] = rb[r]; }
        __syncthreads();
        if (kt + 32 < FEAT / 2) {
#pragma unroll
            for (int r = 0; r < 8; r++) {
                ra[r] = g_feat[aoff[r] + kt + 32];
                rb[r] = Wo[boff[r] + kt + 32];
            }
        }
#pragma unroll
        for (int k = 0; k < 32; k++) {
            float4 a4 = *(const float4*)&As[k * 68 + i0];
            float4 b4 = *(const float4*)&Bs[k * 68 + j0];
            u64 bxy = pk(b4.x, b4.y), bzw = pk(b4.z, b4.w);
            float av[4] = {a4.x, a4.y, a4.z, a4.w};
#pragma unroll
            for (int ii = 0; ii < 4; ii++) {
                u64 aa = pk(av[ii], av[ii]);
                fma2(acc[ii][0], aa, bxy);
                fma2(acc[ii][1], aa, bzw);
            }
        }
        __syncthreads();
    }
#pragma unroll
    for (int ii = 0; ii < 4; ii++) {
        float2 lo = upk(acc[ii][0]), hi = upk(acc[ii][1]);
        float* o = &g_out2[(size_t)z * S * CS + (m0 + i0 + ii) * CS + n0 + j0];
        o[0] = lo.x; o[1] = lo.y; o[2] = hi.x; o[3] = hi.y;
    }
}

// ---------------- K9: combine split-K partials + bias ----------------------
__global__ void k_bias(const float* __restrict__ bo, float* __restrict__ out) {
    int x = blockIdx.x * 256 + threadIdx.x;
    float4 a = ((const float4*)g_out2)[x];
    float4 b = ((const float4*)g_out2)[S * CS / 4 + x];
    int n = (x * 4) % CS;
    float4 bb = *(const float4*)&bo[n];
    ((float4*)out)[x] = make_float4(a.x + b.x + bb.x, a.y + b.y + bb.y,
                                    a.z + b.z + bb.z, a.w + b.w + bb.w);
}

// ---------------------------------------------------------------------------
extern "C" void kernel_launch(void* const* d_in, const int* in_sizes, int n_in,
                              void* d_out, int out_size) {
    const float* single = (const float*)d_in[0];
    const float* pair   = (const float*)d_in[1];
    const float* rot    = (const float*)d_in[2];
    const float* trans  = (const float*)d_in[3];
    const float* Wq     = (const float*)d_in[4];
    const float* Wk     = (const float*)d_in[5];
    const float* Wv     = (const float*)d_in[6];
    const float* Wqp    = (const float*)d_in[7];
    const float* Wkp    = (const float*)d_in[8];
    const float* Wvp    = (const float*)d_in[9];
    const float* Wb     = (const float*)d_in[10];
    const float* Wo     = (const float*)d_in[11];
    const float* bo     = (const float*)d_in[12];
    const float* gamma  = (const float*)d_in[13];
    float* out = (float*)d_out;

    const int SMEM_WPAIR = 4 * 2 * 512 * 16 + 16 * 132 * 4;     // 73984
    const int SMEM_SOFT  = KD * S * 4 + 16 * 32 * 4;            // 91136
    const int SMEM_AV    = 2 * 32 * 132 * 4 + 2 * 128 * 48 * 4; // 82944
    const int SMEM_OPAIR = 8 * 512 * 16 + 8 * 48 * 16;          // 71680
    cudaFuncSetAttribute(k_wpair, cudaFuncAttributeMaxDynamicSharedMemorySize, SMEM_WPAIR);
    cudaFuncSetAttribute(k_soft,  cudaFuncAttributeMaxDynamicSharedMemorySize, SMEM_SOFT);
    cudaFuncSetAttribute(k_av,    cudaFuncAttributeMaxDynamicSharedMemorySize, SMEM_AV);
    cudaFuncSetAttribute(k_opair, cudaFuncAttributeMaxDynamicSharedMemorySize, SMEM_OPAIR);

    k_pre    <<<(S * NH + 255) / 256, 256>>>();          // filler: k_wpair -> launch #4
    k_proj   <<<dim3(NPROJ / 64, S / 32), 256>>>(single, Wq, Wk, Wv, Wqp, Wkp, Wvp);
    k_frames <<<(NH * S + 255) / 256, 256>>>(rot, trans, gamma);
    k_wpair  <<<S, 128, SMEM_WPAIR>>>(pair, Wb);
    k_soft   <<<dim3(S / 16, NH), 512, SMEM_SOFT>>>();
    k_asum2  <<<(NH * S) / 64, 64>>>();
    k_av     <<<dim3(S / 32, NH), 256, SMEM_AV>>>(rot, trans);
    k_opair  <<<S, 256, SMEM_OPAIR>>>(pair);
    k_out    <<<dim3(CS / 64, S / 64, 2), 256>>>(Wo);
    k_bias   <<<(S * CS / 4) / 256, 256>>>(bo, out);
}

// round 17
// speedup vs baseline: 1.2631x; 1.0159x over previous
#include <cuda_runtime.h>
#include <math.h>

#define S     768
#define CS    384
#define CP    128
#define EMB   16
#define NH    12
#define NPROJ 1152          // 3*H*E + 2*H*PQ*3 + H*PV*3
#define FEAT  2112          // H*(E + CP + PV*3 + PV)
#define UC    48            // padded combined [v(16) | lvp(24) | zero-pad(8)]
#define KD    29            // augmented K' dims

typedef unsigned long long u64;

// ---- packed fp32x2 FMA (FFMA2 — PTX-only on sm_103a) --------------------
__device__ __forceinline__ u64 pk(float x, float y) {
    u64 r; asm("mov.b64 %0, {%1,%2};" : "=l"(r) : "f"(x), "f"(y)); return r;
}
__device__ __forceinline__ float2 upk(u64 v) {
    float2 r; asm("mov.b64 {%0,%1}, %2;" : "=f"(r.x), "=f"(r.y) : "l"(v)); return r;
}
__device__ __forceinline__ void fma2(u64& d, u64 a, u64 b) {
    asm("fma.rn.f32x2 %0, %1, %2, %0;" : "+l"(d) : "l"(a), "l"(b));
}
// ---- cp.async helpers -----------------------------------------------------
__device__ __forceinline__ unsigned sptr(const void* p) {
    return (unsigned)__cvta_generic_to_shared(p);
}
#define CP16(dst, src) asm volatile("cp.async.cg.shared.global [%0], [%1], 16;" :: "r"(dst), "l"(src))
#define CP_COMMIT()    asm volatile("cp.async.commit_group;")
#define CP_WAIT1()     asm volatile("cp.async.wait_group 1;" ::: "memory")
// ---- tf32 mma.sync m16n8k8 -------------------------------------------------
#define MMA8(D, A0, A1, A2, A3, B0, B1) \
    asm volatile("mma.sync.aligned.m16n8k8.row.col.f32.tf32.tf32.f32 " \
        "{%0,%1,%2,%3}, {%4,%5,%6,%7}, {%8,%9}, {%0,%1,%2,%3};" \
        : "+f"(D[0]), "+f"(D[1]), "+f"(D[2]), "+f"(D[3]) \
        : "r"(A0), "r"(A1), "r"(A2), "r"(A3), "r"(B0), "r"(B1))

// ---------------- scratch (device globals) --------------------------------
__device__ float g_P[S * NPROJ];
__device__ float g_qp2[NH * S * 32];
__device__ float g_kp2[NH * KD * S];
__device__ float g_U[NH * S * UC];
__device__ float g_wpair[NH * S * S];
__device__ float g_a[NH * S * S];
__device__ float g_asp[NH * 48 * S];      // per-block column partials
__device__ float g_asumT[S * NH];
__device__ float g_feat[S * FEAT];
__device__ float g_out2[2 * S * CS];

// ---------------- K0: filler (positions k_wpair at launch #4 for ncu) ------
__global__ void k_pre() {
    int x = blockIdx.x * 256 + threadIdx.x;
    if (x < S * NH) g_asumT[x] = 0.0f;       // overwritten by k_asum2 later
}

// ---------------- K1: packed projection GEMM (reg double-buffered) --------
__global__ void k_proj(const float* __restrict__ single,
                       const float* __restrict__ Wq, const float* __restrict__ Wk,
                       const float* __restrict__ Wv, const float* __restrict__ Wqp,
                       const float* __restrict__ Wkp, const float* __restrict__ Wvp) {
    __shared__ float As[32 * 36];
    __shared__ float Bs[32 * 68];
    const int n0 = blockIdx.x * 64, m0 = blockIdx.y * 32;
    const int t  = threadIdx.x;
    const int i0 = (t & 15) * 2, j0 = (t >> 4) * 4;

    const float* asrc[4]; int aidx[4];
#pragma unroll
    for (int r = 0; r < 4; r++) {
        int idx = t + 256 * r;
        int i = idx >> 5, k = idx & 31;
        asrc[r] = single + (m0 + i) * CS + k;
        aidx[r] = k * 36 + i;
    }
    const float* bsrc[8]; int bidx[8];
#pragma unroll
    for (int r = 0; r < 8; r++) {
        int idx = t + 256 * r;
        int j = idx >> 5, k = idx & 31;
        int n = n0 + j;
        const float* row;
        if (n < 192)      row = Wq  + n * CS;
        else if (n < 384) row = Wk  + (n - 192) * CS;
        else if (n < 576) row = Wv  + (n - 384) * CS;
        else if (n < 720) row = Wqp + (n - 576) * CS;
        else if (n < 864) row = Wkp + (n - 720) * CS;
        else              row = Wvp + (n - 864) * CS;
        bsrc[r] = row + k;
        bidx[r] = k * 68 + j;
    }
    u64 acc[2][2] = {};
    float ra[4], rb[8];
#pragma unroll
    for (int r = 0; r < 4; r++) ra[r] = asrc[r][0];
#pragma unroll
    for (int r = 0; r < 8; r++) rb[r] = bsrc[r][0];

    for (int kt = 0; kt < CS; kt += 32) {
#pragma unroll
        for (int r = 0; r < 4; r++) As[aidx[r]] = ra[r];
#pragma unroll
        for (int r = 0; r < 8; r++) Bs[bidx[r]] = rb[r];
        __syncthreads();
        if (kt + 32 < CS) {
#pragma unroll
            for (int r = 0; r < 4; r++) ra[r] = asrc[r][kt + 32];
#pragma unroll
            for (int r = 0; r < 8; r++) rb[r] = bsrc[r][kt + 32];
        }
#pragma unroll
        for (int k = 0; k < 32; k++) {
            float2 a2 = *(const float2*)&As[k * 36 + i0];
            float4 b4 = *(const float4*)&Bs[k * 68 + j0];
            u64 bxy = pk(b4.x, b4.y), bzw = pk(b4.z, b4.w);
            u64 ax = pk(a2.x, a2.x), ay = pk(a2.y, a2.y);
            fma2(acc[0][0], ax, bxy); fma2(acc[0][1], ax, bzw);
            fma2(acc[1][0], ay, bxy); fma2(acc[1][1], ay, bzw);
        }
        __syncthreads();
    }
#pragma unroll
    for (int ii = 0; ii < 2; ii++) {
        float2 lo = upk(acc[ii][0]), hi = upk(acc[ii][1]);
        float* o = &g_P[(m0 + i0 + ii) * NPROJ + n0 + j0];
        o[0] = lo.x; o[1] = lo.y; o[2] = hi.x; o[3] = hi.y;
    }
}

// ---------------- K1b: frame apply + augmented Q'/K' build ----------------
__global__ void k_frames(const float* __restrict__ rot, const float* __restrict__ trans,
                         const float* __restrict__ gamma) {
    int idx = blockIdx.x * blockDim.x + threadIdx.x;
    if (idx >= NH * S) return;
    int h = idx / S, s = idx % S;

    float g  = gamma[h];
    float sp = (g > 20.f) ? g : log1pf(expf(g));
    float cf = -0.11785113f * sp;

    float R[3][3], tv[3];
#pragma unroll
    for (int a = 0; a < 3; a++) {
        tv[a] = trans[s * 3 + a];
#pragma unroll
        for (int b = 0; b < 3; b++) R[a][b] = rot[s * 9 + a * 3 + b];
    }
    const float* Ps = g_P + (size_t)s * NPROJ;
    float* qp2 = g_qp2 + (size_t)(h * S + s) * 32;

#pragma unroll
    for (int e = 0; e < EMB; e++) {
        qp2[e] = 0.25f * Ps[h * EMB + e];
        g_kp2[(h * KD + e) * S + s]        = Ps[192 + h * EMB + e];
        g_U[(size_t)(h * S + s) * UC + e]  = Ps[384 + h * EMB + e];
    }
    float m2cf = -2.0f * cf;
#pragma unroll
    for (int p = 0; p < 4; p++) {
        float x0 = Ps[576 + h * 12 + p * 3 + 0];
        float x1 = Ps[576 + h * 12 + p * 3 + 1];
        float x2 = Ps[576 + h * 12 + p * 3 + 2];
#pragma unroll
        for (int a = 0; a < 3; a++) {
            float l = R[a][0] * x0 + R[a][1] * x1 + R[a][2] * x2 + tv[a];
            qp2[16 + p * 3 + a] = m2cf * l;
        }
    }
    qp2[28] = 1.0f; qp2[29] = 0.0f; qp2[30] = 0.0f; qp2[31] = 0.0f;

    float nk = 0.0f;
#pragma unroll
    for (int p = 0; p < 4; p++) {
        float x0 = Ps[720 + h * 12 + p * 3 + 0];
        float x1 = Ps[720 + h * 12 + p * 3 + 1];
        float x2 = Ps[720 + h * 12 + p * 3 + 2];
#pragma unroll
        for (int a = 0; a < 3; a++) {
            float l = R[a][0] * x0 + R[a][1] * x1 + R[a][2] * x2 + tv[a];
            g_kp2[(h * KD + 16 + p * 3 + a) * S + s] = l;
            nk += l * l;
        }
    }
    g_kp2[(h * KD + 28) * S + s] = cf * nk;

#pragma unroll
    for (int p = 0; p < 8; p++) {
        float x0 = Ps[864 + h * 24 + p * 3 + 0];
        float x1 = Ps[864 + h * 24 + p * 3 + 1];
        float x2 = Ps[864 + h * 24 + p * 3 + 2];
#pragma unroll
        for (int a = 0; a < 3; a++)
            g_U[(size_t)(h * S + s) * UC + 16 + p * 3 + a] =
                R[a][0] * x0 + R[a][1] * x1 + R[a][2] * x2 + tv[a];
    }
#pragma unroll
    for (int c = 40; c < UC; c++) g_U[(size_t)(h * S + s) * UC + c] = 0.0f;
}

// ---------------- K2: w_pair — tf32 mma.sync (R16-exact) --------------------
__global__ void __launch_bounds__(128) k_wpair(const float* __restrict__ pair,
                                               const float* __restrict__ Wb) {
    extern __shared__ float sm[];
    float4* buf = (float4*)sm;                   // [4 warps][2 stages][512 f4]
    float*  swb = sm + 4 * 2 * 512 * 4;          // [16][132] tf32 bits
    const int i = blockIdx.x;
    const int t = threadIdx.x;
    const int lane = t & 31, w = t >> 5;

    for (int x = t; x < 16 * 132; x += 128) {
        int row = x / 132, col = x - row * 132;
        float v = (row < NH && col < CP) ? Wb[row * CP + col] : 0.0f;
        unsigned b; asm("cvt.rna.tf32.f32 %0, %1;" : "=r"(b) : "f"(v));
        ((unsigned*)swb)[x] = b;
    }

    float4* wring = buf + w * 1024;
    const float4* gp = (const float4*)pair + (size_t)i * S * 32;

#pragma unroll
    for (int r = 0; r < 16; r++)
        CP16(sptr(&wring[r * 32 + ((lane + r) & 31)]), gp + (w * 16 + r) * 32 + lane);
    CP_COMMIT();
    __syncthreads();

    const unsigned* swbu = (const unsigned*)swb;
    const int r0 = lane >> 2, kb = lane & 3;
    const int h0 = 2 * kb;

    for (int c = 0; c < 12; c++) {
        const unsigned* cur = (const unsigned*)(wring + (c & 1) * 512);
        if (c + 1 < 12) {
            float4* nxt = wring + ((c + 1) & 1) * 512;
            int jt = w + 4 * (c + 1);
#pragma unroll
            for (int r = 0; r < 16; r++)
                CP16(sptr(&nxt[r * 32 + ((lane + r) & 31)]), gp + (jt * 16 + r) * 32 + lane);
        }
        CP_COMMIT();
        CP_WAIT1();

        float d0[4] = {0.f, 0.f, 0.f, 0.f};
        float d1[4] = {0.f, 0.f, 0.f, 0.f};
#pragma unroll
        for (int kc = 0; kc < 16; kc++) {
            int sa = (2 * kc + r0) & 31;
            int sb = (2 * kc + 1 + r0) & 31;
            int sc = (2 * kc + r0 + 8) & 31;
            int sd = (2 * kc + 1 + r0 + 8) & 31;
            unsigned a0 = cur[r0 * 128 + sa * 4 + kb];
            unsigned a1 = cur[(r0 + 8) * 128 + sc * 4 + kb];
            unsigned a2 = cur[r0 * 128 + sb * 4 + kb];
            unsigned a3 = cur[(r0 + 8) * 128 + sd * 4 + kb];
            unsigned b0 = swbu[r0 * 132 + kc * 8 + kb];
            unsigned b1 = swbu[r0 * 132 + kc * 8 + kb + 4];
            unsigned b2 = swbu[(r0 + 8) * 132 + kc * 8 + kb];
            unsigned b3 = swbu[(r0 + 8) * 132 + kc * 8 + kb + 4];
            MMA8(d0, a0, a1, a2, a3, b0, b1);
            MMA8(d1, a0, a1, a2, a3, b2, b3);
        }
        int j = (w + 4 * c) * 16 + r0;
        g_wpair[((size_t)h0 * S + i) * S + j]           = d0[0];
        g_wpair[((size_t)(h0 + 1) * S + i) * S + j]     = d0[1];
        g_wpair[((size_t)h0 * S + i) * S + j + 8]       = d0[2];
        g_wpair[((size_t)(h0 + 1) * S + i) * S + j + 8] = d0[3];
        if (h0 < 4) {
            g_wpair[((size_t)(8 + h0) * S + i) * S + j]     = d1[0];
            g_wpair[((size_t)(9 + h0) * S + i) * S + j]     = d1[1];
            g_wpair[((size_t)(8 + h0) * S + i) * S + j + 8] = d1[2];
            g_wpair[((size_t)(9 + h0) * S + i) * S + j + 8] = d1[3];
        }
    }
}

// ---------------- K3: logits + softmax + fused block column-sums -----------
__global__ void __launch_bounds__(512, 2) k_soft() {
    extern __shared__ float sm[];
    float* ks = sm;                        // [29][768]; reused as stage [16][768]
    float* sq = sm + KD * S;               // [16 rows][32]
    const int h  = blockIdx.y;
    const int i0 = blockIdx.x * 16;
    const int t  = threadIdx.x;

    for (int x = t; x < KD * S; x += 512) ks[x] = g_kp2[(size_t)h * KD * S + x];
    sq[t] = g_qp2[(size_t)(h * S + i0 + (t >> 5)) * 32 + (t & 31)];
    __syncthreads();

    const int w = t >> 5, lane = t & 31;
    const int i = i0 + w;
    const float* wp = g_wpair + ((size_t)h * S + i) * S + lane * 4;

    u64 lo[6], hi[6];
#pragma unroll
    for (int b = 0; b < 6; b++) {
        float4 v = *(const float4*)&wp[b * 128];
        lo[b] = pk(v.x, v.y); hi[b] = pk(v.z, v.w);
    }
#pragma unroll
    for (int e = 0; e < KD; e++) {
        float qe = sq[w * 32 + e];
        u64 q2 = pk(qe, qe);
        const float* kr = ks + e * S + lane * 4;
#pragma unroll
        for (int b = 0; b < 6; b++) {
            float4 kk = *(const float4*)&kr[b * 128];
            fma2(lo[b], q2, pk(kk.x, kk.y));
            fma2(hi[b], q2, pk(kk.z, kk.w));
        }
    }

    float4 l4[6];
    float m = -1e30f;
#pragma unroll
    for (int b = 0; b < 6; b++) {
        float2 a = upk(lo[b]), c = upk(hi[b]);
        l4[b] = make_float4(a.x, a.y, c.x, c.y);
        m = fmaxf(m, fmaxf(fmaxf(a.x, a.y), fmaxf(c.x, c.y)));
    }
#pragma unroll
    for (int o = 16; o > 0; o >>= 1) m = fmaxf(m, __shfl_xor_sync(0xffffffffu, m, o));
    float sum = 0.0f;
#pragma unroll
    for (int b = 0; b < 6; b++) {
        l4[b].x = __expf(l4[b].x - m); l4[b].y = __expf(l4[b].y - m);
        l4[b].z = __expf(l4[b].z - m); l4[b].w = __expf(l4[b].w - m);
        sum += (l4[b].x + l4[b].y) + (l4[b].z + l4[b].w);
    }
#pragma unroll
    for (int o = 16; o > 0; o >>= 1) sum += __shfl_xor_sync(0xffffffffu, sum, o);
    float inv = 1.0f / sum;
    float4 o4[6];
#pragma unroll
    for (int b = 0; b < 6; b++)
        o4[b] = make_float4(l4[b].x * inv, l4[b].y * inv, l4[b].z * inv, l4[b].w * inv);
    float* ap = g_a + ((size_t)h * S + i) * S + lane * 4;
#pragma unroll
    for (int b = 0; b < 6; b++) *(float4*)&ap[b * 128] = o4[b];

    // fused column partial sums (deterministic; reuse ks as [16][768] stage)
    __syncthreads();
    float* stage = ks;
#pragma unroll
    for (int b = 0; b < 6; b++)
        *(float4*)&stage[w * S + lane * 4 + b * 128] = o4[b];
    __syncthreads();
    for (int x = t; x < S; x += 512) {
        float s = 0.f;
#pragma unroll
        for (int r = 0; r < 16; r++) s += stage[r * S + x];
        g_asp[((size_t)h * 48 + blockIdx.x) * S + x] = s;
    }
}

// ---------------- K4: finish column sums ------------------------------------
__global__ void k_asum2() {
    int X = blockIdx.x * 64 + threadIdx.x;       // 0 .. NH*S-1
    int h = X / S, j = X - h * S;
    float s = 0.f;
#pragma unroll 8
    for (int b = 0; b < 48; b++) s += g_asp[((size_t)h * 48 + b) * S + j];
    g_asumT[j * NH + h] = s;
}

// ---------------- K5: o_combined = a @ U + fused inverse-frame scatter -----
__global__ void __launch_bounds__(256) k_av(const float* __restrict__ rot,
                                            const float* __restrict__ trans) {
    extern __shared__ float sm[];
    float* sa = sm;                            // [2][32][132]
    float* su = sm + 2 * 32 * 132;             // [2][128][48]
    const int h  = blockIdx.y;
    const int i0 = blockIdx.x * 32;
    const int t  = threadIdx.x;
    const int i  = t & 31, c0 = (t >> 5) * 6;
    u64 acc[3] = {};

    const float4* ga = (const float4*)g_a;
    const float4* gu = (const float4*)g_U + (size_t)h * S * 12;

#pragma unroll
    for (int r = 0; r < 4; r++) {
        int idx = t + 256 * r;
        int ii = idx >> 5, j4 = idx & 31;
        CP16(sptr(&((float4*)sa)[ii * 33 + j4]),
             ga + ((size_t)h * S + i0 + ii) * (S / 4) + j4);
    }
#pragma unroll
    for (int r = 0; r < 6; r++) {
        int idx = t + 256 * r;
        CP16(sptr(&((float4*)su)[idx]), gu + idx);
    }
    CP_COMMIT();

    for (int c = 0; c < 6; c++) {
        float* sac = sa + (c & 1) * 32 * 132;
        float* suc = su + (c & 1) * 128 * 48;
        if (c + 1 < 6) {
            float* san = sa + ((c + 1) & 1) * 32 * 132;
            float* sun = su + ((c + 1) & 1) * 128 * 48;
            int jt4 = (c + 1) * 32;
#pragma unroll
            for (int r = 0; r < 4; r++) {
                int idx = t + 256 * r;
                int ii = idx >> 5, j4 = idx & 31;
                CP16(sptr(&((float4*)san)[ii * 33 + j4]),
                     ga + ((size_t)h * S + i0 + ii) * (S / 4) + jt4 + j4);
            }
            const float4* gun = gu + (c + 1) * 128 * 12;
#pragma unroll
            for (int r = 0; r < 6; r++) {
                int idx = t + 256 * r;
                CP16(sptr(&((float4*)sun)[idx]), gun + idx);
            }
        }
        CP_COMMIT();
        CP_WAIT1();
        __syncthreads();

#pragma unroll 4
        for (int j = 0; j < 128; j++) {
            float av = sac[i * 132 + j];
            u64 p = pk(av, av);
            const u64* uu = (const u64*)&suc[j * UC + c0];
            fma2(acc[0], p, uu[0]); fma2(acc[1], p, uu[1]); fma2(acc[2], p, uu[2]);
        }
        __syncthreads();
    }

    // stage oc into smem [32][49] then fused inverse-frame scatter
    float* soc = sm;
    __syncthreads();
    {
        float2 v0 = upk(acc[0]), v1 = upk(acc[1]), v2 = upk(acc[2]);
        float* d = soc + i * 49 + c0;
        d[0] = v0.x; d[1] = v0.y; d[2] = v1.x; d[3] = v1.y; d[4] = v2.x; d[5] = v2.y;
    }
    __syncthreads();

    if (t < 32) {
        int s = i0 + t;
        const float* oc = soc + t * 49;
        float* f = g_feat + (size_t)s * FEAT;
#pragma unroll
        for (int e = 0; e < EMB; e++) f[h * EMB + e] = oc[e];

        float R[3][3], tv[3];
#pragma unroll
        for (int a = 0; a < 3; a++) {
            tv[a] = trans[s * 3 + a];
#pragma unroll
            for (int b = 0; b < 3; b++) R[a][b] = rot[s * 9 + a * 3 + b];
        }
#pragma unroll
        for (int p = 0; p < 8; p++) {
            float x0 = oc[16 + p * 3 + 0] - tv[0];
            float x1 = oc[16 + p * 3 + 1] - tv[1];
            float x2 = oc[16 + p * 3 + 2] - tv[2];
            float og[3];
#pragma unroll
            for (int a = 0; a < 3; a++) og[a] = R[0][a] * x0 + R[1][a] * x1 + R[2][a] * x2;
#pragma unroll
            for (int a = 0; a < 3; a++) f[1728 + p * 36 + h * 3 + a] = og[a];
            f[2016 + p * 12 + h] = sqrtf(og[0] * og[0] + og[1] * og[1] + og[2] * og[2]);
        }
    }
}

// ---------------- K7: o_pair — tf32 mma.sync, warp-private A rings ----------
// Per block: one i. GEMM D[c,h] = sum_k pair[i,k,c] * asum[k,h].
// M=128 (8 warps x 16 c), N=16 (h padded), K=768 (12 chunks of 64).
__global__ void __launch_bounds__(256) k_opair(const float* __restrict__ pair) {
    extern __shared__ float sm[];
    float* Abase = sm;                         // [8 warps][2 stages][64 k][16 c]
    float* sasm  = sm + 8 * 2048;              // [768][12] + 16 pad (raw fp32)
    const int i = blockIdx.x;
    const int t = threadIdx.x;
    const int lane = t & 31, w = t >> 5;

    // stage full asum (raw fp32 bits -> tf32 truncation at mma)
    const float4* gs = (const float4*)g_asumT;         // 2304 float4
    for (int x = t; x < 2304; x += 256)
        CP16(sptr(&((float4*)sasm)[x]), gs + x);

    float* wring = Abase + w * 2048;                   // 2 stages x 1024 floats
    const float* gp = pair + (size_t)i * S * CP + w * 16;

    // prefetch chunk 0: k rows 0..63, 16 floats (4 CP16/row)
#pragma unroll
    for (int r = 0; r < 8; r++) {
        int idx = r * 32 + lane;                       // 0..255
        int row = idx >> 2, c4 = idx & 3;
        CP16(sptr(&wring[row * 16 + c4 * 4]), gp + (size_t)row * CP + c4 * 4);
    }
    CP_COMMIT();

    const unsigned* sasu = (const unsigned*)sasm;
    const int r0 = lane >> 2, kb = lane & 3;
    const int h0 = 2 * kb;
    float d0[4] = {0.f, 0.f, 0.f, 0.f};
    float d1[4] = {0.f, 0.f, 0.f, 0.f};

    for (int c = 0; c < 12; c++) {
        const unsigned* cur = (const unsigned*)(wring + (c & 1) * 1024);
        if (c + 1 < 12) {
            float* nxt = wring + ((c + 1) & 1) * 1024;
            const float* gsrc = gp + (size_t)(c + 1) * 64 * CP;
#pragma unroll
            for (int r = 0; r < 8; r++) {
                int idx = r * 32 + lane;
                int row = idx >> 2, c4 = idx & 3;
                CP16(sptr(&nxt[row * 16 + c4 * 4]), gsrc + (size_t)row * CP + c4 * 4);
            }
        }
        CP_COMMIT();
        CP_WAIT1();                                    // per-warp wait
        if (c == 0) __syncthreads();                   // sasm fully visible

        int k0 = c * 64;
#pragma unroll
        for (int kf = 0; kf < 8; kf++) {
            int kl = kf * 8;
            unsigned a0 = cur[(kl + kb) * 16 + r0];
            unsigned a1 = cur[(kl + kb) * 16 + r0 + 8];
            unsigned a2 = cur[(kl + kb + 4) * 16 + r0];
            unsigned a3 = cur[(kl + kb + 4) * 16 + r0 + 8];
            int kg = (k0 + kl + kb) * 12;
            int kg4 = (k0 + kl + kb + 4) * 12;
            unsigned b0 = sasu[kg + r0];
            unsigned b1 = sasu[kg4 + r0];
            unsigned b2 = sasu[kg + 8 + r0];           // h 8..15 (pad-read ok)
            unsigned b3 = sasu[kg4 + 8 + r0];
            MMA8(d0, a0, a1, a2, a3, b0, b1);
            MMA8(d1, a0, a1, a2, a3, b2, b3);
        }
    }

    // scatter: D[m=c][n=h] -> g_feat[i*FEAT + 192 + h*CP + c]
    float* f = g_feat + (size_t)i * FEAT + 192;
    int cg = w * 16 + r0;
    f[h0 * CP + cg]           = d0[0];
    f[(h0 + 1) * CP + cg]     = d0[1];
    f[h0 * CP + cg + 8]       = d0[2];
    f[(h0 + 1) * CP + cg + 8] = d0[3];
    if (h0 < 4) {
        f[(8 + h0) * CP + cg]           = d1[0];
        f[(9 + h0) * CP + cg]           = d1[1];
        f[(8 + h0) * CP + cg + 8]       = d1[2];
        f[(9 + h0) * CP + cg + 8]       = d1[3];
    }
}

// ---------------- K8: out partials = feat @ Wo^T (split-K=2, reg-db) -------
__global__ void k_out(const float* __restrict__ Wo) {
    __shared__ float As[32 * 68];
    __shared__ float Bs[32 * 68];
    const int n0 = blockIdx.x * 64, m0 = blockIdx.y * 64, z = blockIdx.z;
    const int t  = threadIdx.x;
    const int i0 = (t & 15) * 4, j0 = (t >> 4) * 4;
    const int kbase = z * (FEAT / 2);

    int aoff[8], boff[8], aidx[8], bidx[8];
#pragma unroll
    for (int r = 0; r < 8; r++) {
        int idx = t + 256 * r;
        int i = idx >> 5, k = idx & 31;
        aoff[r] = (m0 + i) * FEAT + kbase + k;
        aidx[r] = k * 68 + i;
        boff[r] = (n0 + i) * FEAT + kbase + k;
        bidx[r] = k * 68 + i;
    }
    u64 acc[4][2] = {};
    float ra[8], rb[8];
#pragma unroll
    for (int r = 0; r < 8; r++) { ra[r] = g_feat[aoff[r]]; rb[r] = Wo[boff[r]]; }

    for (int kt = 0; kt < FEAT / 2; kt += 32) {
#pragma unroll
        for (int r = 0; r < 8; r++) { As[aidx[r]] = ra[r]; Bs[bidx[r]] = rb[r]; }
        __syncthreads();
        if (kt + 32 < FEAT / 2) {
#pragma unroll
            for (int r = 0; r < 8; r++) {
                ra[r] = g_feat[aoff[r] + kt + 32];
                rb[r] = Wo[boff[r] + kt + 32];
            }
        }
#pragma unroll
        for (int k = 0; k < 32; k++) {
            float4 a4 = *(const float4*)&As[k * 68 + i0];
            float4 b4 = *(const float4*)&Bs[k * 68 + j0];
            u64 bxy = pk(b4.x, b4.y), bzw = pk(b4.z, b4.w);
            float av[4] = {a4.x, a4.y, a4.z, a4.w};
#pragma unroll
            for (int ii = 0; ii < 4; ii++) {
                u64 aa = pk(av[ii], av[ii]);
                fma2(acc[ii][0], aa, bxy);
                fma2(acc[ii][1], aa, bzw);
            }
        }
        __syncthreads();
    }
#pragma unroll
    for (int ii = 0; ii < 4; ii++) {
        float2 lo = upk(acc[ii][0]), hi = upk(acc[ii][1]);
        float* o = &g_out2[(size_t)z * S * CS + (m0 + i0 + ii) * CS + n0 + j0];
        o[0] = lo.x; o[1] = lo.y; o[2] = hi.x; o[3] = hi.y;
    }
}

// ---------------- K9: combine split-K partials + bias ----------------------
__global__ void k_bias(const float* __restrict__ bo, float* __restrict__ out) {
    int x = blockIdx.x * 256 + threadIdx.x;
    float4 a = ((const float4*)g_out2)[x];
    float4 b = ((const float4*)g_out2)[S * CS / 4 + x];
    int n = (x * 4) % CS;
    float4 bb = *(const float4*)&bo[n];
    ((float4*)out)[x] = make_float4(a.x + b.x + bb.x, a.y + b.y + bb.y,
                                    a.z + b.z + bb.z, a.w + b.w + bb.w);
}

// ---------------------------------------------------------------------------
extern "C" void kernel_launch(void* const* d_in, const int* in_sizes, int n_in,
                              void* d_out, int out_size) {
    const float* single = (const float*)d_in[0];
    const float* pair   = (const float*)d_in[1];
    const float* rot    = (const float*)d_in[2];
    const float* trans  = (const float*)d_in[3];
    const float* Wq     = (const float*)d_in[4];
    const float* Wk     = (const float*)d_in[5];
    const float* Wv     = (const float*)d_in[6];
    const float* Wqp    = (const float*)d_in[7];
    const float* Wkp    = (const float*)d_in[8];
    const float* Wvp    = (const float*)d_in[9];
    const float* Wb     = (const float*)d_in[10];
    const float* Wo     = (const float*)d_in[11];
    const float* bo     = (const float*)d_in[12];
    const float* gamma  = (const float*)d_in[13];
    float* out = (float*)d_out;

    const int SMEM_WPAIR = 4 * 2 * 512 * 16 + 16 * 132 * 4;     // 73984
    const int SMEM_SOFT  = KD * S * 4 + 16 * 32 * 4;            // 91136
    const int SMEM_AV    = 2 * 32 * 132 * 4 + 2 * 128 * 48 * 4; // 82944
    const int SMEM_OPAIR = 8 * 2048 * 4 + (S * NH + 16) * 4;    // 102464
    cudaFuncSetAttribute(k_wpair, cudaFuncAttributeMaxDynamicSharedMemorySize, SMEM_WPAIR);
    cudaFuncSetAttribute(k_soft,  cudaFuncAttributeMaxDynamicSharedMemorySize, SMEM_SOFT);
    cudaFuncSetAttribute(k_av,    cudaFuncAttributeMaxDynamicSharedMemorySize, SMEM_AV);
    cudaFuncSetAttribute(k_opair, cudaFuncAttributeMaxDynamicSharedMemorySize, SMEM_OPAIR);

    k_pre    <<<(S * NH + 255) / 256, 256>>>();          // filler: k_wpair -> launch #4
    k_proj   <<<dim3(NPROJ / 64, S / 32), 256>>>(single, Wq, Wk, Wv, Wqp, Wkp, Wvp);
    k_frames <<<(NH * S + 255) / 256, 256>>>(rot, trans, gamma);
    k_wpair  <<<S, 128, SMEM_WPAIR>>>(pair, Wb);
    k_soft   <<<dim3(S / 16, NH), 512, SMEM_SOFT>>>();
    k_asum2  <<<(NH * S) / 64, 64>>>();
    k_av     <<<dim3(S / 32, NH), 256, SMEM_AV>>>(rot, trans);
    k_opair  <<<S, 256, SMEM_OPAIR>>>(pair);
    k_out    <<<dim3(CS / 64, S / 64, 2), 256>>>(Wo);
    k_bias   <<<(S * CS / 4) / 256, 256>>>(bo, out);
}